// round 14
// baseline (speedup 1.0000x reference)
#include <cuda_runtime.h>
#include <cuda_bf16.h>
#include <cstdint>

#define NN  150000
#define NNP 150016
#define NE  450000
#define NG  5000
#define HH  256
#define H4  64
#define JKD 1536
#define NL  5
#define NBLK 147

// ---------------- scratch ---------------------------------------------------
__device__ float g_jk   [NNP * JKD];
__device__ float g_vn   [NG * HH];
__device__ float g_vnagg[NG * HH];
__device__ __nv_bfloat16 g_ah[NNP * HH];
__device__ __nv_bfloat16 g_al[NNP * HH];
__device__ int g_deg [NN];
__device__ int g_off [NN + 1];
__device__ int g_cur [NN];
__device__ int g_esrc[NE];
__device__ int g_emet[NE];
__device__ int g_bsum[256];
__device__ __nv_bfloat16 g_w1t_hi[NL * HH * HH];
__device__ __nv_bfloat16 g_w1t_lo[NL * HH * HH];
__device__ __nv_bfloat16 g_w2t_hi[NL * HH * HH];
__device__ __nv_bfloat16 g_w2t_lo[NL * HH * HH];
__device__ __nv_bfloat16 g_hw1t_hi[HH * JKD];
__device__ __nv_bfloat16 g_hw1t_lo[HH * JKD];

static __device__ __forceinline__ float4 f4zero() { return make_float4(0.f,0.f,0.f,0.f); }

static __device__ __forceinline__ uint32_t smem_u32(const void* p) {
    uint32_t a;
    asm("{ .reg .u64 t; cvta.to.shared.u64 t, %1; cvt.u32.u64 %0, t; }" : "=r"(a) : "l"(p));
    return a;
}
static __device__ __forceinline__ uint32_t pack_bf(float lo, float hi) {
    uint32_t d;
    asm("cvt.rn.bf16x2.f32 %0, %1, %2;" : "=r"(d) : "f"(hi), "f"(lo));
    return d;
}
static __device__ __forceinline__ void redv4(float* p, float a, float b, float c, float d) {
    asm volatile("red.global.add.v4.f32 [%0], {%1,%2,%3,%4};"
                 :: "l"(p), "f"(a), "f"(b), "f"(c), "f"(d) : "memory");
}
static __device__ __forceinline__ void ldmx4(uint32_t r[4], uint32_t addr) {
    asm volatile("ldmatrix.sync.aligned.m8n8.x4.shared.b16 {%0,%1,%2,%3}, [%4];"
                 : "=r"(r[0]), "=r"(r[1]), "=r"(r[2]), "=r"(r[3]) : "r"(addr));
}
static __device__ __forceinline__ void mma_bf(float c[4], const uint32_t a[4],
                                              uint32_t b0, uint32_t b1) {
    asm volatile("mma.sync.aligned.m16n8k16.row.col.f32.bf16.bf16.f32 "
                 "{%0,%1,%2,%3},{%4,%5,%6,%7},{%8,%9},{%0,%1,%2,%3};"
                 : "+f"(c[0]), "+f"(c[1]), "+f"(c[2]), "+f"(c[3])
                 : "r"(a[0]), "r"(a[1]), "r"(a[2]), "r"(a[3]), "r"(b0), "r"(b1));
}
static __device__ __forceinline__ void cpasync16(uint32_t dst, const void* src) {
    asm volatile("cp.async.cg.shared.global [%0], [%1], 16;" :: "r"(dst), "l"(src));
}
#define CP_COMMIT() asm volatile("cp.async.commit_group;" ::: "memory")
#define CP_WAIT1()  asm volatile("cp.async.wait_group 1;" ::: "memory")
#define CP_WAIT0()  asm volatile("cp.async.wait_group 0;" ::: "memory")

// ---------------- weight prep -----------------------------------------------
__global__ void k_prep(const float* __restrict__ src, __nv_bfloat16* __restrict__ dhi,
                       __nv_bfloat16* __restrict__ dlo, int K, int N, int nmat) {
    int e = blockIdx.x * blockDim.x + threadIdx.x;
    if (e >= nmat * K * N) return;
    int m = e / (K * N), rem = e % (K * N);
    int n = rem / K, k = rem % K;
    float v = src[(size_t)m * K * N + (size_t)k * N + n];
    __nv_bfloat16 h = __float2bfloat16(v);
    __nv_bfloat16 l = __float2bfloat16(v - __bfloat162float(h));
    size_t o = (size_t)m * K * N + (size_t)n * K + k;
    dhi[o] = h; dlo[o] = l;
}

// ---------------- embed -----------------------------------------------------
__global__ void k_embed(const int* __restrict__ x,
                        const float* __restrict__ atom_emb,
                        const float* __restrict__ vn0) {
    int i = blockIdx.x * blockDim.x + threadIdx.x;
    if (i < NG * H4) {
        ((float4*)g_vnagg)[i] = f4zero();
        ((float4*)g_vn)[i] = ((const float4*)vn0)[i & (H4 - 1)];
    }
    if (i < NN) g_deg[i] = 0;
    if (i >= NN * H4) return;
    int n = i >> 6, c4 = i & 63;
    float4 v = ((const float4*)atom_emb)[x[n] * H4 + c4];
    ((float4*)g_jk)[(size_t)n * (JKD / 4) + c4] = v;
}

// ---------------- CSR build --------------------------------------------------
__global__ void k_hist(const int* __restrict__ ei) {
    int e = blockIdx.x * blockDim.x + threadIdx.x;
    if (e < NE) atomicAdd(&g_deg[ei[NE + e]], 1);
}
__global__ void k_scan1() {
    __shared__ int wsum[8];
    int b = blockIdx.x, tid = threadIdx.x;
    int lane = tid & 31, w = tid >> 5;
    int idx = b * 1024 + tid * 4;
    int4 v = make_int4(0, 0, 0, 0);
    if (idx + 3 < NN) v = *(const int4*)(g_deg + idx);
    else {
        if (idx + 0 < NN) v.x = g_deg[idx];
        if (idx + 1 < NN) v.y = g_deg[idx + 1];
        if (idx + 2 < NN) v.z = g_deg[idx + 2];
        if (idx + 3 < NN) v.w = g_deg[idx + 3];
    }
    int s = v.x + v.y + v.z + v.w;
    int t = s;
    #pragma unroll
    for (int o = 1; o < 32; o <<= 1) {
        int u = __shfl_up_sync(0xffffffffu, t, o);
        if (lane >= o) t += u;
    }
    if (lane == 31) wsum[w] = t;
    __syncthreads();
    if (w == 0 && lane < 8) {
        int u = wsum[lane];
        #pragma unroll
        for (int o = 1; o < 8; o <<= 1) {
            int x2 = __shfl_up_sync(0xffu, u, o);
            if (lane >= o) u += x2;
        }
        wsum[lane] = u;
    }
    __syncthreads();
    int excl = t - s + (w > 0 ? wsum[w - 1] : 0);
    if (idx     < NN) g_off[idx]     = excl;
    if (idx + 1 < NN) g_off[idx + 1] = excl + v.x;
    if (idx + 2 < NN) g_off[idx + 2] = excl + v.x + v.y;
    if (idx + 3 < NN) g_off[idx + 3] = excl + v.x + v.y + v.z;
    if (tid == 255) g_bsum[b] = excl + s;
}
__global__ void k_scan2() {
    __shared__ int wsum[8];
    int tid = threadIdx.x, lane = tid & 31, w = tid >> 5;
    int v = (tid < NBLK) ? g_bsum[tid] : 0;
    int t = v;
    #pragma unroll
    for (int o = 1; o < 32; o <<= 1) {
        int u = __shfl_up_sync(0xffffffffu, t, o);
        if (lane >= o) t += u;
    }
    if (lane == 31) wsum[w] = t;
    __syncthreads();
    if (w == 0 && lane < 8) {
        int u = wsum[lane];
        #pragma unroll
        for (int o = 1; o < 8; o <<= 1) {
            int x2 = __shfl_up_sync(0xffu, u, o);
            if (lane >= o) u += x2;
        }
        wsum[lane] = u;
    }
    __syncthreads();
    int excl = t - v + (w > 0 ? wsum[w - 1] : 0);
    if (tid < NBLK) g_bsum[tid] = excl;
}
__global__ void k_scan3() {
    int add = g_bsum[blockIdx.x];
    int idx = blockIdx.x * 1024 + threadIdx.x * 4;
    #pragma unroll
    for (int j = 0; j < 4; j++) {
        if (idx + j < NN) {
            int o = g_off[idx + j] + add;
            g_off[idx + j] = o;
            g_cur[idx + j] = o;
        }
    }
    if (blockIdx.x == 0 && threadIdx.x == 0) g_off[NN] = NE;
}
__global__ void k_fill(const int* __restrict__ ei, const int* __restrict__ ea,
                       const int* __restrict__ batch) {
    int e = blockIdx.x * blockDim.x + threadIdx.x;
    if (e >= NE) return;
    int src = ei[e], dst = ei[NE + e];
    int pos = atomicAdd(&g_cur[dst], 1);
    g_esrc[pos] = src;
    g_emet[pos] = ea[e] | (batch[src] << 2);
}

// ------- gather + GINE combine + bf16 split -> A planes (high occupancy) ----
__global__ void __launch_bounds__(256)
k_agg(const float* __restrict__ bond, const int* __restrict__ batch,
      const float* __restrict__ eps, int l) {
    int warp = threadIdx.x >> 5, lane = threadIdx.x & 31;
    int node = blockIdx.x * 8 + warp;
    if (node >= NN) return;
    int beg = g_off[node], end = g_off[node + 1];
    float4 a0 = f4zero(), a1 = f4zero();
    const float* hb = g_jk + (size_t)l * HH + lane * 8;
    const float* vb = g_vn + lane * 8;
    const float* bb = bond + lane * 8;
    for (int base = beg; base < end; base += 32) {
        int n = end - base; if (n > 32) n = 32;
        int s = 0, m = 0;
        if (lane < n) { s = g_esrc[base + lane]; m = g_emet[base + lane]; }
        for (int j = 0; j < n; j++) {
            int src = __shfl_sync(0xffffffffu, s, j);
            int mt  = __shfl_sync(0xffffffffu, m, j);
            const float* hp = hb + (size_t)src * JKD;
            const float* vp = vb + (mt >> 2) * HH;
            const float* bp = bb + (mt & 3) * HH;
            float4 h0 = *(const float4*)hp, h1 = *(const float4*)(hp + 4);
            float4 v0 = *(const float4*)vp, v1 = *(const float4*)(vp + 4);
            float4 e0 = *(const float4*)bp, e1 = *(const float4*)(bp + 4);
            a0.x += fmaxf(h0.x + v0.x + e0.x, 0.f);
            a0.y += fmaxf(h0.y + v0.y + e0.y, 0.f);
            a0.z += fmaxf(h0.z + v0.z + e0.z, 0.f);
            a0.w += fmaxf(h0.w + v0.w + e0.w, 0.f);
            a1.x += fmaxf(h1.x + v1.x + e1.x, 0.f);
            a1.y += fmaxf(h1.y + v1.y + e1.y, 0.f);
            a1.z += fmaxf(h1.z + v1.z + e1.z, 0.f);
            a1.w += fmaxf(h1.w + v1.w + e1.w, 0.f);
        }
    }
    const float alpha = 1.f + __ldg(&eps[l]);
    const float* hp2 = g_jk + (size_t)node * JKD + (size_t)l * HH + lane * 8;
    const float* vp2 = g_vn + (size_t)__ldg(&batch[node]) * HH + lane * 8;
    float4 h0 = *(const float4*)hp2, h1 = *(const float4*)(hp2 + 4);
    float4 v0 = *(const float4*)vp2, v1 = *(const float4*)(vp2 + 4);
    float f[8];
    f[0] = fmaf(alpha, h0.x + v0.x, a0.x);
    f[1] = fmaf(alpha, h0.y + v0.y, a0.y);
    f[2] = fmaf(alpha, h0.z + v0.z, a0.z);
    f[3] = fmaf(alpha, h0.w + v0.w, a0.w);
    f[4] = fmaf(alpha, h1.x + v1.x, a1.x);
    f[5] = fmaf(alpha, h1.y + v1.y, a1.y);
    f[6] = fmaf(alpha, h1.z + v1.z, a1.z);
    f[7] = fmaf(alpha, h1.w + v1.w, a1.w);
    uint32_t hi[4], lo[4];
    #pragma unroll
    for (int q = 0; q < 4; q++) {
        float f0 = f[2*q], f1 = f[2*q+1];
        __nv_bfloat16 b0 = __float2bfloat16(f0), b1 = __float2bfloat16(f1);
        hi[q] = ((uint32_t)__bfloat16_as_ushort(b1) << 16) | __bfloat16_as_ushort(b0);
        lo[q] = pack_bf(f0 - __bfloat162float(b0), f1 - __bfloat162float(b1));
    }
    ((uint4*)(g_ah + (size_t)node * HH))[lane] = make_uint4(hi[0], hi[1], hi[2], hi[3]);
    ((uint4*)(g_al + (size_t)node * HH))[lane] = make_uint4(lo[0], lo[1], lo[2], lo[3]);
}

// ===================== fused layer megakernel (BM=64, occ 2) ================
#define AROW    80
#define A64_SZ  (64 * AROW)             // 5120 per plane
#define B64_SZ  (256 * AROW)            // 20480 per plane
#define STG64   (2 * A64_SZ + 2 * B64_SZ) // 51200
#define T64ROWB 1040                    // t row: 512 hi | 512 lo | 16 pad
#define T64_LO  512
#define T64_SZ  (64 * T64ROWB)          // 66560
#define B2_OFF  T64_SZ
#define R2ROW   80                      // B2 row: 32 hi | 32 lo | 16 pad
#define B2_LO   32
#define B2_STG  (256 * R2ROW)           // 20480 per stage
#define SMEM_L  (B2_OFF + 2 * B2_STG)   // 107520 (>= 2*STG64 = 102400)
#define SMEM_H  (2 * STG64)             // 102400
#define ZROW    260

__global__ void __launch_bounds__(256, 2)
k_layer(const int* __restrict__ batch, const float* __restrict__ vn, int layer,
        const __nv_bfloat16* __restrict__ B1h, const __nv_bfloat16* __restrict__ B1l,
        const float* __restrict__ bias1,
        const __nv_bfloat16* __restrict__ B2h, const __nv_bfloat16* __restrict__ B2l,
        const float* __restrict__ bias2,
        const float* __restrict__ lng, const float* __restrict__ lnb) {
    extern __shared__ __align__(128) char smem[];
    const int tid = threadIdx.x, warp = tid >> 5, lane = tid & 31;
    const int brow = blockIdx.x * 64;
    const int wm = warp & 1, wn = warp >> 1;   // 2 x 4 warp grid
    const uint32_t sb = smem_u32(smem);

    const int ar = tid >> 2, aq = tid & 3;     // A row 0..63, quarter
    const __nv_bfloat16* Ahp = g_ah + (size_t)(brow + ar) * HH + aq * 8;
    const __nv_bfloat16* Alp = g_al + (size_t)(brow + ar) * HH + aq * 8;
    const __nv_bfloat16* B1ph = B1h + (size_t)tid * HH;
    const __nv_bfloat16* B1pl = B1l + (size_t)tid * HH;
    const __nv_bfloat16* B2ph = B2h + (size_t)tid * HH;
    const __nv_bfloat16* B2pl = B2l + (size_t)tid * HH;

    const uint32_t a1_addr = sb + (uint32_t)(wm * 32 + (lane & 15)) * AROW + (lane >> 4) * 16;
    const int bn = wn * 64 + (lane & 7) + ((lane >> 4) << 3);
    const uint32_t b1_addr = sb + 2 * A64_SZ + (uint32_t)bn * AROW + ((lane >> 3) & 1) * 16;
    const uint32_t a2_addr = sb + (uint32_t)(wm * 32 + (lane & 15)) * T64ROWB + (lane >> 4) * 16;
    const uint32_t b2_addr = sb + B2_OFF + (uint32_t)bn * R2ROW + ((lane >> 3) & 1) * 16;

    float acc[2][8][4];
    #pragma unroll
    for (int mi = 0; mi < 2; mi++)
        #pragma unroll
        for (int ni = 0; ni < 8; ni++)
            #pragma unroll
            for (int j = 0; j < 4; j++) acc[mi][ni][j] = 0.f;

    auto issueP1 = [&](int c) {
        uint32_t base = sb + (uint32_t)(c & 1) * STG64;
        uint32_t adst = base + (uint32_t)ar * AROW + aq * 16;
        cpasync16(adst,          Ahp + c * 32);
        cpasync16(adst + A64_SZ, Alp + c * 32);
        uint32_t bdst = base + 2 * A64_SZ + (uint32_t)tid * AROW;
        const char* bh = (const char*)(B1ph + c * 32);
        const char* bl = (const char*)(B1pl + c * 32);
        #pragma unroll
        for (int j = 0; j < 4; j++) {
            cpasync16(bdst + j * 16,          bh + j * 16);
            cpasync16(bdst + B64_SZ + j * 16, bl + j * 16);
        }
        CP_COMMIT();
    };
    auto issueB2 = [&](int c) {
        uint32_t bdst = sb + B2_OFF + (uint32_t)(c & 1) * B2_STG + (uint32_t)tid * R2ROW;
        const char* bh = (const char*)(B2ph + c * 16);
        const char* bl = (const char*)(B2pl + c * 16);
        cpasync16(bdst,           bh);
        cpasync16(bdst + 16,      bh + 16);
        cpasync16(bdst + B2_LO,        bl);      // lo interleaved at +32
        cpasync16(bdst + B2_LO + 16,   bl + 16); // hmm: overlaps hi! fix below
        CP_COMMIT();
    };
    // NOTE: B2 row layout is [hi 32B | lo 32B | pad 16]; hi at 0..31, lo at 32..63.
    auto mma_block1 = [&](uint32_t aBase, uint32_t bBase) {
        #pragma unroll
        for (int k16 = 0; k16 < 2; k16++) {
            uint32_t ah[2][4], al[2][4];
            #pragma unroll
            for (int mi = 0; mi < 2; mi++) {
                uint32_t aa = aBase + mi * 16 * AROW + k16 * 32;
                ldmx4(ah[mi], aa);
                ldmx4(al[mi], aa + A64_SZ);
            }
            #pragma unroll
            for (int np = 0; np < 4; np++) {
                uint32_t ba = bBase + np * 16 * AROW + k16 * 32;
                uint32_t bh[4], bl[4];
                ldmx4(bh, ba);
                ldmx4(bl, ba + B64_SZ);
                #pragma unroll
                for (int g = 0; g < 2; g++) {
                    #pragma unroll
                    for (int mi = 0; mi < 2; mi++) {
                        float* cc = acc[mi][np * 2 + g];
                        mma_bf(cc, ah[mi], bh[2*g], bh[2*g+1]);
                        mma_bf(cc, ah[mi], bl[2*g], bl[2*g+1]);
                        mma_bf(cc, al[mi], bh[2*g], bh[2*g+1]);
                    }
                }
            }
        }
    };

    // ---------------- phase 1: GEMM1 (2-stage, double-sync) ----------------
    issueP1(0);
    #pragma unroll
    for (int c = 0; c < 8; c++) {
        if (c + 1 < 8) { issueP1(c + 1); CP_WAIT1(); } else { CP_WAIT0(); }
        __syncthreads();
        mma_block1(a1_addr + (uint32_t)(c & 1) * STG64, b1_addr + (uint32_t)(c & 1) * STG64);
        __syncthreads();
    }

    // early B2 prefetch (overlaps t writeback)
    issueB2(0);

    // -------- t -> smem interleaved bf16 planes (bias + relu + split) ------
    #pragma unroll
    for (int mi = 0; mi < 2; mi++) {
        int r = wm * 32 + mi * 16 + (lane >> 2);
        #pragma unroll
        for (int ni = 0; ni < 8; ni++) {
            int col = wn * 64 + ni * 8 + (lane & 3) * 2;
            float b0 = __ldg(&bias1[col]), b1v = __ldg(&bias1[col + 1]);
            float v0 = fmaxf(acc[mi][ni][0] + b0, 0.f);
            float v1 = fmaxf(acc[mi][ni][1] + b1v, 0.f);
            float v2 = fmaxf(acc[mi][ni][2] + b0, 0.f);
            float v3 = fmaxf(acc[mi][ni][3] + b1v, 0.f);
            __nv_bfloat16 h0 = __float2bfloat16(v0), h1 = __float2bfloat16(v1);
            __nv_bfloat16 h2 = __float2bfloat16(v2), h3 = __float2bfloat16(v3);
            uint32_t off0 = (uint32_t)r * T64ROWB + col * 2;
            uint32_t off1 = (uint32_t)(r + 8) * T64ROWB + col * 2;
            *(uint32_t*)(smem + off0) = ((uint32_t)__bfloat16_as_ushort(h1) << 16) | __bfloat16_as_ushort(h0);
            *(uint32_t*)(smem + off1) = ((uint32_t)__bfloat16_as_ushort(h3) << 16) | __bfloat16_as_ushort(h2);
            *(uint32_t*)(smem + off0 + T64_LO) = pack_bf(v0 - __bfloat162float(h0), v1 - __bfloat162float(h1));
            *(uint32_t*)(smem + off1 + T64_LO) = pack_bf(v2 - __bfloat162float(h2), v3 - __bfloat162float(h3));
        }
    }

    #pragma unroll
    for (int mi = 0; mi < 2; mi++)
        #pragma unroll
        for (int ni = 0; ni < 8; ni++)
            #pragma unroll
            for (int j = 0; j < 4; j++) acc[mi][ni][j] = 0.f;

    __syncthreads();

    // ------------ phase 2: GEMM2 (16 k16-chunks, 2-stage, double-sync) -----
    #pragma unroll
    for (int c = 0; c < 16; c++) {
        if (c + 1 < 16) { issueB2(c + 1); CP_WAIT1(); } else { CP_WAIT0(); }
        __syncthreads();
        uint32_t ah[2][4], al[2][4];
        #pragma unroll
        for (int mi = 0; mi < 2; mi++) {
            uint32_t aa = a2_addr + mi * 16 * T64ROWB + c * 32;
            ldmx4(ah[mi], aa);
            ldmx4(al[mi], aa + T64_LO);
        }
        uint32_t bbase = b2_addr + (uint32_t)(c & 1) * B2_STG;
        #pragma unroll
        for (int np = 0; np < 4; np++) {
            uint32_t ba = bbase + np * 16 * R2ROW;
            uint32_t bh[4], bl[4];
            ldmx4(bh, ba);
            ldmx4(bl, ba + B2_LO);
            #pragma unroll
            for (int g = 0; g < 2; g++) {
                #pragma unroll
                for (int mi = 0; mi < 2; mi++) {
                    float* cc = acc[mi][np * 2 + g];
                    mma_bf(cc, ah[mi], bh[2*g], bh[2*g+1]);
                    mma_bf(cc, ah[mi], bl[2*g], bl[2*g+1]);
                    mma_bf(cc, al[mi], bh[2*g], bh[2*g+1]);
                }
            }
        }
        __syncthreads();
    }

    // ---------------- LN epilogue -----------------------------------------
    float* zs = (float*)smem;
    #pragma unroll
    for (int mi = 0; mi < 2; mi++) {
        int rl = wm * 32 + mi * 16 + (lane >> 2);
        #pragma unroll
        for (int ni = 0; ni < 8; ni++) {
            int col = wn * 64 + ni * 8 + (lane & 3) * 2;
            float b0 = __ldg(&bias2[col]), b1v = __ldg(&bias2[col + 1]);
            *(float2*)(zs + (size_t)rl * ZROW + col) =
                make_float2(acc[mi][ni][0] + b0, acc[mi][ni][1] + b1v);
            *(float2*)(zs + (size_t)(rl + 8) * ZROW + col) =
                make_float2(acc[mi][ni][2] + b0, acc[mi][ni][3] + b1v);
        }
    }
    __syncthreads();
    #pragma unroll
    for (int rr = 0; rr < 8; rr++) {
        int row = warp * 8 + rr;
        int grow = brow + row;
        float4 a4 = *(float4*)(zs + (size_t)row * ZROW + lane * 8);
        float4 b4 = *(float4*)(zs + (size_t)row * ZROW + lane * 8 + 4);
        float s  = a4.x + a4.y + a4.z + a4.w + b4.x + b4.y + b4.z + b4.w;
        float ss = a4.x*a4.x + a4.y*a4.y + a4.z*a4.z + a4.w*a4.w
                 + b4.x*b4.x + b4.y*b4.y + b4.z*b4.z + b4.w*b4.w;
        #pragma unroll
        for (int o = 16; o; o >>= 1) {
            s  += __shfl_xor_sync(0xffffffffu, s,  o);
            ss += __shfl_xor_sync(0xffffffffu, ss, o);
        }
        if (grow >= NN) continue;
        float mean = s * (1.f / HH);
        float var  = ss * (1.f / HH) - mean * mean;
        float rstd = rsqrtf(var + 1e-5f);
        float4 g0 = ((const float4*)lng)[lane * 2], g1 = ((const float4*)lng)[lane * 2 + 1];
        float4 c0 = ((const float4*)lnb)[lane * 2], c1 = ((const float4*)lnb)[lane * 2 + 1];
        const float4* hv = (const float4*)(g_jk + (size_t)grow * JKD + (size_t)layer * HH);
        int bidx = __ldg(&batch[grow]);
        const float4* vv = (const float4*)(vn + (size_t)bidx * HH);
        float4 h0 = hv[lane * 2], h1 = hv[lane * 2 + 1];
        float4 w0 = vv[lane * 2], w1 = vv[lane * 2 + 1];
        float4 o0, o1;
        o0.x = fmaxf((a4.x - mean) * rstd * g0.x + c0.x, 0.f) + h0.x + w0.x;
        o0.y = fmaxf((a4.y - mean) * rstd * g0.y + c0.y, 0.f) + h0.y + w0.y;
        o0.z = fmaxf((a4.z - mean) * rstd * g0.z + c0.z, 0.f) + h0.z + w0.z;
        o0.w = fmaxf((a4.w - mean) * rstd * g0.w + c0.w, 0.f) + h0.w + w0.w;
        o1.x = fmaxf((b4.x - mean) * rstd * g1.x + c1.x, 0.f) + h1.x + w1.x;
        o1.y = fmaxf((b4.y - mean) * rstd * g1.y + c1.y, 0.f) + h1.y + w1.y;
        o1.z = fmaxf((b4.z - mean) * rstd * g1.z + c1.z, 0.f) + h1.z + w1.z;
        o1.w = fmaxf((b4.w - mean) * rstd * g1.w + c1.w, 0.f) + h1.w + w1.w;
        float4* jkp = (float4*)(g_jk + (size_t)grow * JKD + (size_t)(layer + 1) * HH);
        jkp[lane * 2]     = o0;
        jkp[lane * 2 + 1] = o1;
        float* va = g_vnagg + (size_t)bidx * HH + lane * 8;
        redv4(va,     o0.x, o0.y, o0.z, o0.w);
        redv4(va + 4, o1.x, o1.y, o1.z, o1.w);
    }
}

// ---- head: t = relu(jk @ hw1 + hb1); out = t @ hw2 + hb2 (BM=64, occ 2) ----
__global__ void __launch_bounds__(256, 2)
k_head(const __nv_bfloat16* __restrict__ Bh, const __nv_bfloat16* __restrict__ Bl,
       const float* __restrict__ bias1,
       const float* __restrict__ w2, const float* __restrict__ b2,
       float* __restrict__ out) {
    extern __shared__ __align__(128) char smem[];
    const int tid = threadIdx.x, warp = tid >> 5, lane = tid & 31;
    const int brow = blockIdx.x * 64;
    const int wm = warp & 1, wn = warp >> 1;
    const uint32_t sb = smem_u32(smem);
    const int nch = JKD / 32;   // 48

    const int ar = tid >> 2, aq = tid & 3;
    const float* Ap = g_jk + (size_t)(brow + ar) * JKD + aq * 8;
    const __nv_bfloat16* Bph = Bh + (size_t)tid * JKD;
    const __nv_bfloat16* Bpl = Bl + (size_t)tid * JKD;

    const uint32_t a_addr = sb + (uint32_t)(wm * 32 + (lane & 15)) * AROW + (lane >> 4) * 16;
    const int bn = wn * 64 + (lane & 7) + ((lane >> 4) << 3);
    const uint32_t b_addr = sb + 2 * A64_SZ + (uint32_t)bn * AROW + ((lane >> 3) & 1) * 16;

    float acc[2][8][4];
    #pragma unroll
    for (int mi = 0; mi < 2; mi++)
        #pragma unroll
        for (int ni = 0; ni < 8; ni++)
            #pragma unroll
            for (int j = 0; j < 4; j++) acc[mi][ni][j] = 0.f;

    auto ldgA = [&](int c, float f[8]) {
        const float* ap = Ap + c * 32;
        *(float4*)(f)     = *(const float4*)(ap);
        *(float4*)(f + 4) = *(const float4*)(ap + 4);
    };
    auto stsA = [&](int c, const float f[8]) {
        uint32_t hi[4], lo[4];
        #pragma unroll
        for (int q = 0; q < 4; q++) {
            float f0 = f[2*q], f1 = f[2*q+1];
            __nv_bfloat16 h0 = __float2bfloat16(f0), h1 = __float2bfloat16(f1);
            hi[q] = ((uint32_t)__bfloat16_as_ushort(h1) << 16) | __bfloat16_as_ushort(h0);
            lo[q] = pack_bf(f0 - __bfloat162float(h0), f1 - __bfloat162float(h1));
        }
        char* p = smem + (c & 1) * STG64 + ar * AROW + aq * 16;
        *(uint4*)(p)          = make_uint4(hi[0], hi[1], hi[2], hi[3]);
        *(uint4*)(p + A64_SZ) = make_uint4(lo[0], lo[1], lo[2], lo[3]);
    };
    auto issueB = [&](int c) {
        uint32_t bdst = sb + (uint32_t)(c & 1) * STG64 + 2 * A64_SZ + (uint32_t)tid * AROW;
        const char* bh = (const char*)(Bph + c * 32);
        const char* bl = (const char*)(Bpl + c * 32);
        #pragma unroll
        for (int j = 0; j < 4; j++) {
            cpasync16(bdst + j * 16,          bh + j * 16);
            cpasync16(bdst + B64_SZ + j * 16, bl + j * 16);
        }
        CP_COMMIT();
    };

    {
        float f0[8];
        ldgA(0, f0); issueB(0); stsA(0, f0);
        for (int c = 0; c < nch; c++) {
            bool pre = (c + 1 < nch);
            float fn[8];
            if (pre) { ldgA(c + 1, fn); issueB(c + 1); CP_WAIT1(); } else { CP_WAIT0(); }
            __syncthreads();
            if (pre) stsA(c + 1, fn);   // stage 1-s; safe: mma(c-1) done at prev trailing sync
            uint32_t so = (uint32_t)(c & 1) * STG64;
            #pragma unroll
            for (int k16 = 0; k16 < 2; k16++) {
                uint32_t ah[2][4], al[2][4];
                #pragma unroll
                for (int mi = 0; mi < 2; mi++) {
                    uint32_t aa = a_addr + so + mi * 16 * AROW + k16 * 32;
                    ldmx4(ah[mi], aa);
                    ldmx4(al[mi], aa + A64_SZ);
                }
                #pragma unroll
                for (int np = 0; np < 4; np++) {
                    uint32_t ba = b_addr + so + np * 16 * AROW + k16 * 32;
                    uint32_t bh[4], bl[4];
                    ldmx4(bh, ba);
                    ldmx4(bl, ba + B64_SZ);
                    #pragma unroll
                    for (int g = 0; g < 2; g++) {
                        #pragma unroll
                        for (int mi = 0; mi < 2; mi++) {
                            float* cc = acc[mi][np * 2 + g];
                            mma_bf(cc, ah[mi], bh[2*g], bh[2*g+1]);
                            mma_bf(cc, ah[mi], bl[2*g], bl[2*g+1]);
                            mma_bf(cc, al[mi], bh[2*g], bh[2*g+1]);
                        }
                    }
                }
            }
            __syncthreads();
        }
    }

    // ---- fused head2: stage t=relu(acc+b1) and w2; out = t @ w2 + b2 -------
    float* zs = (float*)smem;
    float* w2s = zs + 64 * ZROW;
    #pragma unroll
    for (int mi = 0; mi < 2; mi++) {
        int rl = wm * 32 + mi * 16 + (lane >> 2);
        #pragma unroll
        for (int ni = 0; ni < 8; ni++) {
            int col = wn * 64 + ni * 8 + (lane & 3) * 2;
            float b0 = __ldg(&bias1[col]), b1v = __ldg(&bias1[col + 1]);
            *(float2*)(zs + (size_t)rl * ZROW + col) =
                make_float2(fmaxf(acc[mi][ni][0] + b0, 0.f), fmaxf(acc[mi][ni][1] + b1v, 0.f));
            *(float2*)(zs + (size_t)(rl + 8) * ZROW + col) =
                make_float2(fmaxf(acc[mi][ni][2] + b0, 0.f), fmaxf(acc[mi][ni][3] + b1v, 0.f));
        }
    }
    for (int i = tid; i < HH * 28; i += 256) w2s[i] = __ldg(&w2[i]);
    __syncthreads();

    #pragma unroll
    for (int rr = 0; rr < 8; rr++) {
        int row = warp * 8 + rr;
        int grow = brow + row;
        if (grow >= NN || lane >= 28) continue;
        const float* zr = zs + (size_t)row * ZROW;
        float a = 0.f;
        #pragma unroll 8
        for (int k = 0; k < HH; k++) a = fmaf(zr[k], w2s[k * 28 + lane], a);
        out[(size_t)grow * 28 + lane] = a + __ldg(&b2[lane]);
    }
}

// ------- virtual node v2: 32 graphs/block, smem weight tiles ----------------
#define VG 32
#define VROW 260
#define SMEM_V ((VG * VROW + 64 * HH) * 4)

__global__ void __launch_bounds__(256)
k_vn(const float* __restrict__ w, const float* __restrict__ bias,
     const float* __restrict__ lng, const float* __restrict__ lnb) {
    extern __shared__ __align__(16) float vsm[];
    float* vnin = vsm;
    float* wt   = vsm + VG * VROW;
    int tid = threadIdx.x;
    int g0 = blockIdx.x * VG;

    for (int i = tid; i < VG * HH; i += 256) {
        int g = i >> 8, c = i & 255;
        int gid = g0 + g;
        float v = 0.f;
        if (gid < NG) {
            v = g_vnagg[(size_t)gid * HH + c] + g_vn[(size_t)gid * HH + c];
            g_vnagg[(size_t)gid * HH + c] = 0.f;
        }
        vnin[g * VROW + c] = v;
    }

    int gl = tid >> 3, sub = tid & 7;
    float acc[32];
    #pragma unroll
    for (int j = 0; j < 32; j++) acc[j] = 0.f;

    for (int kt = 0; kt < 4; kt++) {
        __syncthreads();
        for (int v4 = tid; v4 < 4096; v4 += 256) {
            int k = v4 >> 6, c4 = v4 & 63;
            ((float4*)wt)[k * 64 + c4] = ((const float4*)w)[(size_t)(kt * 64 + k) * 64 + c4];
        }
        __syncthreads();
        for (int k = 0; k < 64; k++) {
            float xv = vnin[gl * VROW + kt * 64 + k];
            const float* wr = wt + k * 256 + sub;
            #pragma unroll
            for (int j = 0; j < 32; j++) acc[j] = fmaf(xv, wr[8 * j], acc[j]);
        }
    }

    float s = 0.f, ss = 0.f;
    float y[32];
    #pragma unroll
    for (int j = 0; j < 32; j++) {
        y[j] = acc[j] + __ldg(&bias[sub + 8 * j]);
        s += y[j]; ss += y[j] * y[j];
    }
    #pragma unroll
    for (int o = 1; o < 8; o <<= 1) {
        s  += __shfl_xor_sync(0xffffffffu, s,  o);
        ss += __shfl_xor_sync(0xffffffffu, ss, o);
    }
    float mean = s * (1.f / HH);
    float var  = ss * (1.f / HH) - mean * mean;
    float rstd = rsqrtf(var + 1e-5f);
    int gid = g0 + gl;
    if (gid < NG) {
        #pragma unroll
        for (int j = 0; j < 32; j++) {
            int col = sub + 8 * j;
            float z = (y[j] - mean) * rstd * __ldg(&lng[col]) + __ldg(&lnb[col]);
            g_vn[(size_t)gid * HH + col] = fmaxf(z, 0.f);
        }
    }
}

// ---------------------------------------------------------------------------
extern "C" void kernel_launch(void* const* d_in, const int* in_sizes, int n_in,
                              void* d_out, int out_size) {
    const int*   x     = (const int*)  d_in[0];
    const int*   ei    = (const int*)  d_in[1];
    const int*   ea    = (const int*)  d_in[2];
    const int*   batch = (const int*)  d_in[3];
    const float* aemb  = (const float*)d_in[4];
    const float* bemb  = (const float*)d_in[5];
    const float* vn0   = (const float*)d_in[6];
    const float* w1    = (const float*)d_in[7];
    const float* b1    = (const float*)d_in[8];
    const float* w2    = (const float*)d_in[9];
    const float* b2    = (const float*)d_in[10];
    const float* eps   = (const float*)d_in[11];
    const float* lng   = (const float*)d_in[12];
    const float* lnb   = (const float*)d_in[13];
    const float* vnw   = (const float*)d_in[14];
    const float* vnb   = (const float*)d_in[15];
    const float* vlg   = (const float*)d_in[16];
    const float* vlb   = (const float*)d_in[17];
    const float* hw1   = (const float*)d_in[18];
    const float* hb1   = (const float*)d_in[19];
    const float* hw2   = (const float*)d_in[20];
    const float* hb2   = (const float*)d_in[21];
    float* out = (float*)d_out;

    float *p_vn;
    cudaGetSymbolAddress((void**)&p_vn, g_vn);
    __nv_bfloat16 *w1h, *w1l, *w2h, *w2l, *hwh, *hwl;
    cudaGetSymbolAddress((void**)&w1h, g_w1t_hi);
    cudaGetSymbolAddress((void**)&w1l, g_w1t_lo);
    cudaGetSymbolAddress((void**)&w2h, g_w2t_hi);
    cudaGetSymbolAddress((void**)&w2l, g_w2t_lo);
    cudaGetSymbolAddress((void**)&hwh, g_hw1t_hi);
    cudaGetSymbolAddress((void**)&hwl, g_hw1t_lo);

    cudaFuncSetAttribute(k_layer, cudaFuncAttributeMaxDynamicSharedMemorySize, SMEM_L);
    cudaFuncSetAttribute(k_head,  cudaFuncAttributeMaxDynamicSharedMemorySize, SMEM_H);
    cudaFuncSetAttribute(k_vn,    cudaFuncAttributeMaxDynamicSharedMemorySize, SMEM_V);

    const int nb_nh = (NN * H4 + 255) / 256;
    const int ggrid = NNP / 64;   // 2344

    k_prep<<<(NL * HH * HH + 255) / 256, 256>>>(w1, w1h, w1l, HH, HH, NL);
    k_prep<<<(NL * HH * HH + 255) / 256, 256>>>(w2, w2h, w2l, HH, HH, NL);
    k_prep<<<(JKD * HH + 255) / 256, 256>>>(hw1, hwh, hwl, JKD, HH, 1);

    k_embed<<<nb_nh, 256>>>(x, aemb, vn0);
    k_hist<<<(NE + 255) / 256, 256>>>(ei);
    k_scan1<<<NBLK, 256>>>();
    k_scan2<<<1, 256>>>();
    k_scan3<<<NBLK, 256>>>();
    k_fill<<<(NE + 255) / 256, 256>>>(ei, ea, batch);

    for (int l = 0; l < NL; l++) {
        k_agg<<<(NN + 7) / 8, 256>>>(bemb, batch, eps, l);
        k_layer<<<ggrid, 256, SMEM_L>>>(
            batch, p_vn, l,
            w1h + (size_t)l * HH * HH, w1l + (size_t)l * HH * HH, b1 + l * HH,
            w2h + (size_t)l * HH * HH, w2l + (size_t)l * HH * HH, b2 + l * HH,
            lng + l * HH, lnb + l * HH);
        k_vn<<<(NG + VG - 1) / VG, 256, SMEM_V>>>(
            vnw + (size_t)l * HH * HH, vnb + l * HH, vlg + l * HH, vlb + l * HH);
    }

    k_head<<<ggrid, 256, SMEM_H>>>(hwh, hwl, hb1, hw2, hb2, out);
}

// round 15
// speedup vs baseline: 1.0782x; 1.0782x over previous
#include <cuda_runtime.h>
#include <cuda_bf16.h>
#include <cstdint>

#define NN  150000
#define NNP 150016
#define NE  450000
#define NG  5000
#define HH  256
#define H4  64
#define JKD 1536
#define NL  5
#define NBLK 147

// ---------------- scratch ---------------------------------------------------
__device__ float g_jk   [NNP * JKD];
__device__ __nv_bfloat16 g_jkh[NNP * JKD];   // bf16 hi plane of jk (head A operand)
__device__ __nv_bfloat16 g_jkl[NNP * JKD];   // bf16 lo plane
__device__ float g_vn   [NG * HH];
__device__ float g_vnagg[NG * HH];
__device__ __nv_bfloat16 g_ah[NNP * HH];
__device__ __nv_bfloat16 g_al[NNP * HH];
__device__ int g_deg [NN];
__device__ int g_off [NN + 1];
__device__ int g_cur [NN];
__device__ int g_esrc[NE];
__device__ int g_emet[NE];
__device__ int g_bsum[256];
__device__ __nv_bfloat16 g_w1t_hi[NL * HH * HH];
__device__ __nv_bfloat16 g_w1t_lo[NL * HH * HH];
__device__ __nv_bfloat16 g_w2t_hi[NL * HH * HH];
__device__ __nv_bfloat16 g_w2t_lo[NL * HH * HH];
__device__ __nv_bfloat16 g_hw1t_hi[HH * JKD];
__device__ __nv_bfloat16 g_hw1t_lo[HH * JKD];

static __device__ __forceinline__ float4 f4zero() { return make_float4(0.f,0.f,0.f,0.f); }

static __device__ __forceinline__ uint32_t smem_u32(const void* p) {
    uint32_t a;
    asm("{ .reg .u64 t; cvta.to.shared.u64 t, %1; cvt.u32.u64 %0, t; }" : "=r"(a) : "l"(p));
    return a;
}
static __device__ __forceinline__ uint32_t pack_bf(float lo, float hi) {
    uint32_t d;
    asm("cvt.rn.bf16x2.f32 %0, %1, %2;" : "=r"(d) : "f"(hi), "f"(lo));
    return d;
}
static __device__ __forceinline__ uint32_t pack_hi(float f0, float f1) {
    __nv_bfloat16 h0 = __float2bfloat16(f0), h1 = __float2bfloat16(f1);
    return ((uint32_t)__bfloat16_as_ushort(h1) << 16) | __bfloat16_as_ushort(h0);
}
static __device__ __forceinline__ uint32_t pack_lo(float f0, float f1) {
    __nv_bfloat16 h0 = __float2bfloat16(f0), h1 = __float2bfloat16(f1);
    return pack_bf(f0 - __bfloat162float(h0), f1 - __bfloat162float(h1));
}
static __device__ __forceinline__ void redv4(float* p, float a, float b, float c, float d) {
    asm volatile("red.global.add.v4.f32 [%0], {%1,%2,%3,%4};"
                 :: "l"(p), "f"(a), "f"(b), "f"(c), "f"(d) : "memory");
}
static __device__ __forceinline__ void ldmx4(uint32_t r[4], uint32_t addr) {
    asm volatile("ldmatrix.sync.aligned.m8n8.x4.shared.b16 {%0,%1,%2,%3}, [%4];"
                 : "=r"(r[0]), "=r"(r[1]), "=r"(r[2]), "=r"(r[3]) : "r"(addr));
}
static __device__ __forceinline__ void mma_bf(float c[4], const uint32_t a[4],
                                              uint32_t b0, uint32_t b1) {
    asm volatile("mma.sync.aligned.m16n8k16.row.col.f32.bf16.bf16.f32 "
                 "{%0,%1,%2,%3},{%4,%5,%6,%7},{%8,%9},{%0,%1,%2,%3};"
                 : "+f"(c[0]), "+f"(c[1]), "+f"(c[2]), "+f"(c[3])
                 : "r"(a[0]), "r"(a[1]), "r"(a[2]), "r"(a[3]), "r"(b0), "r"(b1));
}
static __device__ __forceinline__ void cpasync16(uint32_t dst, const void* src) {
    asm volatile("cp.async.cg.shared.global [%0], [%1], 16;" :: "r"(dst), "l"(src));
}
#define CP_COMMIT() asm volatile("cp.async.commit_group;" ::: "memory")
#define CP_WAIT2()  asm volatile("cp.async.wait_group 2;" ::: "memory")
#define CP_WAIT1()  asm volatile("cp.async.wait_group 1;" ::: "memory")
#define CP_WAIT0()  asm volatile("cp.async.wait_group 0;" ::: "memory")

// ---------------- weight prep -----------------------------------------------
__global__ void k_prep(const float* __restrict__ src, __nv_bfloat16* __restrict__ dhi,
                       __nv_bfloat16* __restrict__ dlo, int K, int N, int nmat) {
    int e = blockIdx.x * blockDim.x + threadIdx.x;
    if (e >= nmat * K * N) return;
    int m = e / (K * N), rem = e % (K * N);
    int n = rem / K, k = rem % K;
    float v = src[(size_t)m * K * N + (size_t)k * N + n];
    __nv_bfloat16 h = __float2bfloat16(v);
    __nv_bfloat16 l = __float2bfloat16(v - __bfloat162float(h));
    size_t o = (size_t)m * K * N + (size_t)n * K + k;
    dhi[o] = h; dlo[o] = l;
}

// ---------------- embed (also writes bf16 jk planes slice 0) ----------------
__global__ void k_embed(const int* __restrict__ x,
                        const float* __restrict__ atom_emb,
                        const float* __restrict__ vn0) {
    int i = blockIdx.x * blockDim.x + threadIdx.x;
    if (i < NG * H4) {
        ((float4*)g_vnagg)[i] = f4zero();
        ((float4*)g_vn)[i] = ((const float4*)vn0)[i & (H4 - 1)];
    }
    if (i < NN) g_deg[i] = 0;
    if (i >= NN * H4) return;
    int n = i >> 6, c4 = i & 63;
    float4 v = ((const float4*)atom_emb)[x[n] * H4 + c4];
    ((float4*)g_jk)[(size_t)n * (JKD / 4) + c4] = v;
    size_t eo = (size_t)n * JKD + c4 * 4;
    uint2 hv = make_uint2(pack_hi(v.x, v.y), pack_hi(v.z, v.w));
    uint2 lv = make_uint2(pack_lo(v.x, v.y), pack_lo(v.z, v.w));
    *(uint2*)(g_jkh + eo) = hv;
    *(uint2*)(g_jkl + eo) = lv;
}

// ---------------- CSR build --------------------------------------------------
__global__ void k_hist(const int* __restrict__ ei) {
    int e = blockIdx.x * blockDim.x + threadIdx.x;
    if (e < NE) atomicAdd(&g_deg[ei[NE + e]], 1);
}
__global__ void k_scan1() {
    __shared__ int wsum[8];
    int b = blockIdx.x, tid = threadIdx.x;
    int lane = tid & 31, w = tid >> 5;
    int idx = b * 1024 + tid * 4;
    int4 v = make_int4(0, 0, 0, 0);
    if (idx + 3 < NN) v = *(const int4*)(g_deg + idx);
    else {
        if (idx + 0 < NN) v.x = g_deg[idx];
        if (idx + 1 < NN) v.y = g_deg[idx + 1];
        if (idx + 2 < NN) v.z = g_deg[idx + 2];
        if (idx + 3 < NN) v.w = g_deg[idx + 3];
    }
    int s = v.x + v.y + v.z + v.w;
    int t = s;
    #pragma unroll
    for (int o = 1; o < 32; o <<= 1) {
        int u = __shfl_up_sync(0xffffffffu, t, o);
        if (lane >= o) t += u;
    }
    if (lane == 31) wsum[w] = t;
    __syncthreads();
    if (w == 0 && lane < 8) {
        int u = wsum[lane];
        #pragma unroll
        for (int o = 1; o < 8; o <<= 1) {
            int x2 = __shfl_up_sync(0xffu, u, o);
            if (lane >= o) u += x2;
        }
        wsum[lane] = u;
    }
    __syncthreads();
    int excl = t - s + (w > 0 ? wsum[w - 1] : 0);
    if (idx     < NN) g_off[idx]     = excl;
    if (idx + 1 < NN) g_off[idx + 1] = excl + v.x;
    if (idx + 2 < NN) g_off[idx + 2] = excl + v.x + v.y;
    if (idx + 3 < NN) g_off[idx + 3] = excl + v.x + v.y + v.z;
    if (tid == 255) g_bsum[b] = excl + s;
}
__global__ void k_scan2() {
    __shared__ int wsum[8];
    int tid = threadIdx.x, lane = tid & 31, w = tid >> 5;
    int v = (tid < NBLK) ? g_bsum[tid] : 0;
    int t = v;
    #pragma unroll
    for (int o = 1; o < 32; o <<= 1) {
        int u = __shfl_up_sync(0xffffffffu, t, o);
        if (lane >= o) t += u;
    }
    if (lane == 31) wsum[w] = t;
    __syncthreads();
    if (w == 0 && lane < 8) {
        int u = wsum[lane];
        #pragma unroll
        for (int o = 1; o < 8; o <<= 1) {
            int x2 = __shfl_up_sync(0xffu, u, o);
            if (lane >= o) u += x2;
        }
        wsum[lane] = u;
    }
    __syncthreads();
    int excl = t - v + (w > 0 ? wsum[w - 1] : 0);
    if (tid < NBLK) g_bsum[tid] = excl;
}
__global__ void k_scan3() {
    int add = g_bsum[blockIdx.x];
    int idx = blockIdx.x * 1024 + threadIdx.x * 4;
    #pragma unroll
    for (int j = 0; j < 4; j++) {
        if (idx + j < NN) {
            int o = g_off[idx + j] + add;
            g_off[idx + j] = o;
            g_cur[idx + j] = o;
        }
    }
    if (blockIdx.x == 0 && threadIdx.x == 0) g_off[NN] = NE;
}
__global__ void k_fill(const int* __restrict__ ei, const int* __restrict__ ea,
                       const int* __restrict__ batch) {
    int e = blockIdx.x * blockDim.x + threadIdx.x;
    if (e >= NE) return;
    int src = ei[e], dst = ei[NE + e];
    int pos = atomicAdd(&g_cur[dst], 1);
    g_esrc[pos] = src;
    g_emet[pos] = ea[e] | (batch[src] << 2);
}

// ------- gather + GINE combine + bf16 split -> A planes (high occupancy) ----
__global__ void __launch_bounds__(256)
k_agg(const float* __restrict__ bond, const int* __restrict__ batch,
      const float* __restrict__ eps, int l) {
    int warp = threadIdx.x >> 5, lane = threadIdx.x & 31;
    int node = blockIdx.x * 8 + warp;
    if (node >= NN) return;
    int beg = g_off[node], end = g_off[node + 1];
    float4 a0 = f4zero(), a1 = f4zero();
    const float* hb = g_jk + (size_t)l * HH + lane * 8;
    const float* vb = g_vn + lane * 8;
    const float* bb = bond + lane * 8;
    for (int base = beg; base < end; base += 32) {
        int n = end - base; if (n > 32) n = 32;
        int s = 0, m = 0;
        if (lane < n) { s = g_esrc[base + lane]; m = g_emet[base + lane]; }
        for (int j = 0; j < n; j++) {
            int src = __shfl_sync(0xffffffffu, s, j);
            int mt  = __shfl_sync(0xffffffffu, m, j);
            const float* hp = hb + (size_t)src * JKD;
            const float* vp = vb + (mt >> 2) * HH;
            const float* bp = bb + (mt & 3) * HH;
            float4 h0 = *(const float4*)hp, h1 = *(const float4*)(hp + 4);
            float4 v0 = *(const float4*)vp, v1 = *(const float4*)(vp + 4);
            float4 e0 = *(const float4*)bp, e1 = *(const float4*)(bp + 4);
            a0.x += fmaxf(h0.x + v0.x + e0.x, 0.f);
            a0.y += fmaxf(h0.y + v0.y + e0.y, 0.f);
            a0.z += fmaxf(h0.z + v0.z + e0.z, 0.f);
            a0.w += fmaxf(h0.w + v0.w + e0.w, 0.f);
            a1.x += fmaxf(h1.x + v1.x + e1.x, 0.f);
            a1.y += fmaxf(h1.y + v1.y + e1.y, 0.f);
            a1.z += fmaxf(h1.z + v1.z + e1.z, 0.f);
            a1.w += fmaxf(h1.w + v1.w + e1.w, 0.f);
        }
    }
    const float alpha = 1.f + __ldg(&eps[l]);
    const float* hp2 = g_jk + (size_t)node * JKD + (size_t)l * HH + lane * 8;
    const float* vp2 = g_vn + (size_t)__ldg(&batch[node]) * HH + lane * 8;
    float4 h0 = *(const float4*)hp2, h1 = *(const float4*)(hp2 + 4);
    float4 v0 = *(const float4*)vp2, v1 = *(const float4*)(vp2 + 4);
    float f[8];
    f[0] = fmaf(alpha, h0.x + v0.x, a0.x);
    f[1] = fmaf(alpha, h0.y + v0.y, a0.y);
    f[2] = fmaf(alpha, h0.z + v0.z, a0.z);
    f[3] = fmaf(alpha, h0.w + v0.w, a0.w);
    f[4] = fmaf(alpha, h1.x + v1.x, a1.x);
    f[5] = fmaf(alpha, h1.y + v1.y, a1.y);
    f[6] = fmaf(alpha, h1.z + v1.z, a1.z);
    f[7] = fmaf(alpha, h1.w + v1.w, a1.w);
    uint32_t hi[4], lo[4];
    #pragma unroll
    for (int q = 0; q < 4; q++) {
        hi[q] = pack_hi(f[2*q], f[2*q+1]);
        lo[q] = pack_lo(f[2*q], f[2*q+1]);
    }
    ((uint4*)(g_ah + (size_t)node * HH))[lane] = make_uint4(hi[0], hi[1], hi[2], hi[3]);
    ((uint4*)(g_al + (size_t)node * HH))[lane] = make_uint4(lo[0], lo[1], lo[2], lo[3]);
}

// ===================== fused layer megakernel (R11 best config) =============
#define ROWB   80
#define A_SZ   (128 * ROWB)
#define B_SZ   (256 * ROWB)
#define STG    (2 * A_SZ + 2 * B_SZ) // 61440 (Ah|Al|Bh|Bl)
#define TROW   528
#define TP_SZ  (128 * TROW)
#define B2_OFF (2 * TP_SZ)           // 135168
#define ROW2B  48
#define B2P_SZ (256 * ROW2B)         // 12288 per plane
#define B2_STG2 (2 * B2P_SZ)         // 24576 per stage, 3 stages
#define SMEM_L (B2_OFF + 3 * B2_STG2) // 208896
#define SMEM_H (3 * STG)              // 184320
#define ZROW   260

__global__ void __launch_bounds__(512, 1)
k_layer(const int* __restrict__ batch, const float* __restrict__ vn, int layer,
        const __nv_bfloat16* __restrict__ B1h, const __nv_bfloat16* __restrict__ B1l,
        const float* __restrict__ bias1,
        const __nv_bfloat16* __restrict__ B2h, const __nv_bfloat16* __restrict__ B2l,
        const float* __restrict__ bias2,
        const float* __restrict__ lng, const float* __restrict__ lnb) {
    extern __shared__ __align__(128) char smem[];
    const int tid = threadIdx.x, warp = tid >> 5, lane = tid & 31;
    const int brow = blockIdx.x * 128;
    const int wm = warp & 3, wn = warp >> 2;
    const uint32_t sb = smem_u32(smem);

    const int ar = tid >> 2, aq = tid & 3;
    const __nv_bfloat16* Ahp = g_ah + (size_t)(brow + ar) * HH + aq * 8;
    const __nv_bfloat16* Alp = g_al + (size_t)(brow + ar) * HH + aq * 8;
    const int bplane = tid >> 8, brw = tid & 255;
    const __nv_bfloat16* B1p = (bplane ? B1l : B1h) + (size_t)brw * HH;
    const __nv_bfloat16* B2p = (bplane ? B2l : B2h) + (size_t)brw * HH;

    const uint32_t a1_addr = sb + (uint32_t)(wm * 32 + (lane & 15)) * ROWB + (lane >> 4) * 16;
    const int bn = wn * 64 + (lane & 7) + ((lane >> 4) << 3);
    const uint32_t b1_addr = sb + 2 * A_SZ + (uint32_t)bn * ROWB + ((lane >> 3) & 1) * 16;
    const uint32_t a2_addr = sb + (uint32_t)(wm * 32 + (lane & 15)) * TROW + (lane >> 4) * 16;
    const uint32_t b2_addr = sb + B2_OFF + (uint32_t)bn * ROW2B + ((lane >> 3) & 1) * 16;

    float acc[2][8][4];
    #pragma unroll
    for (int mi = 0; mi < 2; mi++)
        #pragma unroll
        for (int ni = 0; ni < 8; ni++)
            #pragma unroll
            for (int j = 0; j < 4; j++) acc[mi][ni][j] = 0.f;

    auto issueP1 = [&](int c) {
        uint32_t base = sb + (uint32_t)(c % 3) * STG;
        uint32_t adst = base + (uint32_t)ar * ROWB + aq * 16;
        cpasync16(adst,        Ahp + c * 32);
        cpasync16(adst + A_SZ, Alp + c * 32);
        uint32_t bdst = base + 2 * A_SZ + bplane * B_SZ + brw * ROWB;
        const char* bsrc = (const char*)(B1p + c * 32);
        #pragma unroll
        for (int j = 0; j < 4; j++) cpasync16(bdst + j * 16, bsrc + j * 16);
        CP_COMMIT();
    };
    auto issueB2 = [&](int c) {
        uint32_t bdst = sb + B2_OFF + (uint32_t)(c % 3) * B2_STG2 + bplane * B2P_SZ + brw * ROW2B;
        const char* bsrc = (const char*)(B2p + c * 16);
        cpasync16(bdst,      bsrc);
        cpasync16(bdst + 16, bsrc + 16);
        CP_COMMIT();
    };
    auto mma_block1 = [&](uint32_t aBase, uint32_t bBase) {
        #pragma unroll
        for (int k16 = 0; k16 < 2; k16++) {
            uint32_t ah[2][4], al[2][4];
            #pragma unroll
            for (int mi = 0; mi < 2; mi++) {
                uint32_t aa = aBase + mi * 16 * ROWB + k16 * 32;
                ldmx4(ah[mi], aa);
                ldmx4(al[mi], aa + A_SZ);
            }
            #pragma unroll
            for (int np = 0; np < 4; np++) {
                uint32_t ba = bBase + np * 16 * ROWB + k16 * 32;
                uint32_t bh[4], bl[4];
                ldmx4(bh, ba);
                ldmx4(bl, ba + B_SZ);
                #pragma unroll
                for (int g = 0; g < 2; g++) {
                    #pragma unroll
                    for (int mi = 0; mi < 2; mi++) {
                        float* cc = acc[mi][np * 2 + g];
                        mma_bf(cc, ah[mi], bh[2*g], bh[2*g+1]);
                        mma_bf(cc, ah[mi], bl[2*g], bl[2*g+1]);
                        mma_bf(cc, al[mi], bh[2*g], bh[2*g+1]);
                    }
                }
            }
        }
    };

    // ---------------- phase 1: GEMM1 (3-stage ring, 1 sync/chunk) ----------
    issueP1(0); issueP1(1);
    #pragma unroll
    for (int c = 0; c < 8; c++) {
        if (c + 1 < 8) { CP_WAIT1(); } else { CP_WAIT0(); }
        __syncthreads();
        if (c + 2 < 8) issueP1(c + 2);
        uint32_t so = (uint32_t)(c % 3) * STG;
        mma_block1(a1_addr + so, b1_addr + so);
    }
    __syncthreads();

    // early B2 prefetch (overlaps t writeback)
    issueB2(0); issueB2(1);

    // ---------------- t -> smem bf16 planes (bias + relu + split) ---------
    #pragma unroll
    for (int mi = 0; mi < 2; mi++) {
        int r = wm * 32 + mi * 16 + (lane >> 2);
        #pragma unroll
        for (int ni = 0; ni < 8; ni++) {
            int col = wn * 64 + ni * 8 + (lane & 3) * 2;
            float b0 = __ldg(&bias1[col]), b1v = __ldg(&bias1[col + 1]);
            float v0 = fmaxf(acc[mi][ni][0] + b0, 0.f);
            float v1 = fmaxf(acc[mi][ni][1] + b1v, 0.f);
            float v2 = fmaxf(acc[mi][ni][2] + b0, 0.f);
            float v3 = fmaxf(acc[mi][ni][3] + b1v, 0.f);
            uint32_t off0 = (uint32_t)r * TROW + col * 2;
            uint32_t off1 = (uint32_t)(r + 8) * TROW + col * 2;
            *(uint32_t*)(smem + off0) = pack_hi(v0, v1);
            *(uint32_t*)(smem + off1) = pack_hi(v2, v3);
            *(uint32_t*)(smem + TP_SZ + off0) = pack_lo(v0, v1);
            *(uint32_t*)(smem + TP_SZ + off1) = pack_lo(v2, v3);
        }
    }

    #pragma unroll
    for (int mi = 0; mi < 2; mi++)
        #pragma unroll
        for (int ni = 0; ni < 8; ni++)
            #pragma unroll
            for (int j = 0; j < 4; j++) acc[mi][ni][j] = 0.f;

    __syncthreads();

    // ---------------- phase 2: GEMM2 (16 k16-chunks, 3-stage ring) --------
    #pragma unroll
    for (int c = 0; c < 16; c++) {
        if (c + 1 < 16) { CP_WAIT1(); } else { CP_WAIT0(); }
        __syncthreads();
        if (c + 2 < 16) issueB2(c + 2);
        uint32_t ah[2][4], al[2][4];
        #pragma unroll
        for (int mi = 0; mi < 2; mi++) {
            uint32_t aa = a2_addr + mi * 16 * TROW + c * 32;
            ldmx4(ah[mi], aa);
            ldmx4(al[mi], aa + TP_SZ);
        }
        uint32_t bbase = b2_addr + (uint32_t)(c % 3) * B2_STG2;
        #pragma unroll
        for (int np = 0; np < 4; np++) {
            uint32_t ba = bbase + np * 16 * ROW2B;
            uint32_t bh[4], bl[4];
            ldmx4(bh, ba);
            ldmx4(bl, ba + B2P_SZ);
            #pragma unroll
            for (int g = 0; g < 2; g++) {
                #pragma unroll
                for (int mi = 0; mi < 2; mi++) {
                    float* cc = acc[mi][np * 2 + g];
                    mma_bf(cc, ah[mi], bh[2*g], bh[2*g+1]);
                    mma_bf(cc, ah[mi], bl[2*g], bl[2*g+1]);
                    mma_bf(cc, al[mi], bh[2*g], bh[2*g+1]);
                }
            }
        }
    }
    __syncthreads();

    // ---------------- LN epilogue (also writes bf16 jk planes) -------------
    float* zs = (float*)smem;
    #pragma unroll
    for (int mi = 0; mi < 2; mi++) {
        int rl = wm * 32 + mi * 16 + (lane >> 2);
        #pragma unroll
        for (int ni = 0; ni < 8; ni++) {
            int col = wn * 64 + ni * 8 + (lane & 3) * 2;
            float b0 = __ldg(&bias2[col]), b1v = __ldg(&bias2[col + 1]);
            *(float2*)(zs + (size_t)rl * ZROW + col) =
                make_float2(acc[mi][ni][0] + b0, acc[mi][ni][1] + b1v);
            *(float2*)(zs + (size_t)(rl + 8) * ZROW + col) =
                make_float2(acc[mi][ni][2] + b0, acc[mi][ni][3] + b1v);
        }
    }
    __syncthreads();
    #pragma unroll
    for (int rr = 0; rr < 8; rr++) {
        int row = warp * 8 + rr;
        int grow = brow + row;
        float4 a4 = *(float4*)(zs + (size_t)row * ZROW + lane * 8);
        float4 b4 = *(float4*)(zs + (size_t)row * ZROW + lane * 8 + 4);
        float s  = a4.x + a4.y + a4.z + a4.w + b4.x + b4.y + b4.z + b4.w;
        float ss = a4.x*a4.x + a4.y*a4.y + a4.z*a4.z + a4.w*a4.w
                 + b4.x*b4.x + b4.y*b4.y + b4.z*b4.z + b4.w*b4.w;
        #pragma unroll
        for (int o = 16; o; o >>= 1) {
            s  += __shfl_xor_sync(0xffffffffu, s,  o);
            ss += __shfl_xor_sync(0xffffffffu, ss, o);
        }
        if (grow >= NN) continue;
        float mean = s * (1.f / HH);
        float var  = ss * (1.f / HH) - mean * mean;
        float rstd = rsqrtf(var + 1e-5f);
        float4 g0 = ((const float4*)lng)[lane * 2], g1 = ((const float4*)lng)[lane * 2 + 1];
        float4 c0 = ((const float4*)lnb)[lane * 2], c1 = ((const float4*)lnb)[lane * 2 + 1];
        const float4* hv = (const float4*)(g_jk + (size_t)grow * JKD + (size_t)layer * HH);
        int bidx = __ldg(&batch[grow]);
        const float4* vv = (const float4*)(vn + (size_t)bidx * HH);
        float4 h0 = hv[lane * 2], h1 = hv[lane * 2 + 1];
        float4 w0 = vv[lane * 2], w1 = vv[lane * 2 + 1];
        float4 o0, o1;
        o0.x = fmaxf((a4.x - mean) * rstd * g0.x + c0.x, 0.f) + h0.x + w0.x;
        o0.y = fmaxf((a4.y - mean) * rstd * g0.y + c0.y, 0.f) + h0.y + w0.y;
        o0.z = fmaxf((a4.z - mean) * rstd * g0.z + c0.z, 0.f) + h0.z + w0.z;
        o0.w = fmaxf((a4.w - mean) * rstd * g0.w + c0.w, 0.f) + h0.w + w0.w;
        o1.x = fmaxf((b4.x - mean) * rstd * g1.x + c1.x, 0.f) + h1.x + w1.x;
        o1.y = fmaxf((b4.y - mean) * rstd * g1.y + c1.y, 0.f) + h1.y + w1.y;
        o1.z = fmaxf((b4.z - mean) * rstd * g1.z + c1.z, 0.f) + h1.z + w1.z;
        o1.w = fmaxf((b4.w - mean) * rstd * g1.w + c1.w, 0.f) + h1.w + w1.w;
        size_t jo = (size_t)grow * JKD + (size_t)(layer + 1) * HH;
        float4* jkp = (float4*)(g_jk + jo);
        jkp[lane * 2]     = o0;
        jkp[lane * 2 + 1] = o1;
        // bf16 split planes for the head GEMM
        *(uint4*)(g_jkh + jo + lane * 8) = make_uint4(
            pack_hi(o0.x, o0.y), pack_hi(o0.z, o0.w),
            pack_hi(o1.x, o1.y), pack_hi(o1.z, o1.w));
        *(uint4*)(g_jkl + jo + lane * 8) = make_uint4(
            pack_lo(o0.x, o0.y), pack_lo(o0.z, o0.w),
            pack_lo(o1.x, o1.y), pack_lo(o1.z, o1.w));
        float* va = g_vnagg + (size_t)bidx * HH + lane * 8;
        redv4(va,     o0.x, o0.y, o0.z, o0.w);
        redv4(va + 4, o1.x, o1.y, o1.z, o1.w);
    }
}

// ---- head: t = relu(jk @ hw1 + hb1); out = t @ hw2 + hb2 (pure cp.async) ---
__global__ void __launch_bounds__(512, 1)
k_head(const __nv_bfloat16* __restrict__ Bh, const __nv_bfloat16* __restrict__ Bl,
       const float* __restrict__ bias1,
       const float* __restrict__ w2, const float* __restrict__ b2,
       float* __restrict__ out) {
    extern __shared__ __align__(128) char smem[];
    const int tid = threadIdx.x, warp = tid >> 5, lane = tid & 31;
    const int brow = blockIdx.x * 128;
    const int wm = warp & 3, wn = warp >> 2;
    const uint32_t sb = smem_u32(smem);
    const int nch = JKD / 32;   // 48

    const int ar = tid >> 2, aq = tid & 3;
    const __nv_bfloat16* Jh = g_jkh + (size_t)(brow + ar) * JKD + aq * 8;
    const __nv_bfloat16* Jl = g_jkl + (size_t)(brow + ar) * JKD + aq * 8;
    const int bplane = tid >> 8, brw = tid & 255;
    const __nv_bfloat16* Bp = (bplane ? Bl : Bh) + (size_t)brw * JKD;

    const uint32_t a_addr = sb + (uint32_t)(wm * 32 + (lane & 15)) * ROWB + (lane >> 4) * 16;
    const int bn = wn * 64 + (lane & 7) + ((lane >> 4) << 3);
    const uint32_t b_addr = sb + 2 * A_SZ + (uint32_t)bn * ROWB + ((lane >> 3) & 1) * 16;

    float acc[2][8][4];
    #pragma unroll
    for (int mi = 0; mi < 2; mi++)
        #pragma unroll
        for (int ni = 0; ni < 8; ni++)
            #pragma unroll
            for (int j = 0; j < 4; j++) acc[mi][ni][j] = 0.f;

    auto issueH = [&](int c) {
        uint32_t base = sb + (uint32_t)(c % 3) * STG;
        uint32_t adst = base + (uint32_t)ar * ROWB + aq * 16;
        cpasync16(adst,        Jh + c * 32);
        cpasync16(adst + A_SZ, Jl + c * 32);
        uint32_t bdst = base + 2 * A_SZ + bplane * B_SZ + brw * ROWB;
        const char* bsrc = (const char*)(Bp + c * 32);
        #pragma unroll
        for (int j = 0; j < 4; j++) cpasync16(bdst + j * 16, bsrc + j * 16);
        CP_COMMIT();
    };

    issueH(0); issueH(1);
    for (int c = 0; c < nch; c++) {
        if (c + 1 < nch) { CP_WAIT1(); } else { CP_WAIT0(); }
        __syncthreads();
        if (c + 2 < nch) issueH(c + 2);
        uint32_t so = (uint32_t)(c % 3) * STG;
        #pragma unroll
        for (int k16 = 0; k16 < 2; k16++) {
            uint32_t ah[2][4], al[2][4];
            #pragma unroll
            for (int mi = 0; mi < 2; mi++) {
                uint32_t aa = a_addr + so + mi * 16 * ROWB + k16 * 32;
                ldmx4(ah[mi], aa);
                ldmx4(al[mi], aa + A_SZ);
            }
            #pragma unroll
            for (int np = 0; np < 4; np++) {
                uint32_t ba = b_addr + so + np * 16 * ROWB + k16 * 32;
                uint32_t bh[4], bl[4];
                ldmx4(bh, ba);
                ldmx4(bl, ba + B_SZ);
                #pragma unroll
                for (int g = 0; g < 2; g++) {
                    #pragma unroll
                    for (int mi = 0; mi < 2; mi++) {
                        float* cc = acc[mi][np * 2 + g];
                        mma_bf(cc, ah[mi], bh[2*g], bh[2*g+1]);
                        mma_bf(cc, ah[mi], bl[2*g], bl[2*g+1]);
                        mma_bf(cc, al[mi], bh[2*g], bh[2*g+1]);
                    }
                }
            }
        }
    }
    __syncthreads();

    // ---- fused head2: stage t=relu(acc+b1) and w2; out = t @ w2 + b2 -------
    float* zs = (float*)smem;
    float* w2s = zs + 128 * ZROW;
    #pragma unroll
    for (int mi = 0; mi < 2; mi++) {
        int rl = wm * 32 + mi * 16 + (lane >> 2);
        #pragma unroll
        for (int ni = 0; ni < 8; ni++) {
            int col = wn * 64 + ni * 8 + (lane & 3) * 2;
            float b0 = __ldg(&bias1[col]), b1v = __ldg(&bias1[col + 1]);
            *(float2*)(zs + (size_t)rl * ZROW + col) =
                make_float2(fmaxf(acc[mi][ni][0] + b0, 0.f), fmaxf(acc[mi][ni][1] + b1v, 0.f));
            *(float2*)(zs + (size_t)(rl + 8) * ZROW + col) =
                make_float2(fmaxf(acc[mi][ni][2] + b0, 0.f), fmaxf(acc[mi][ni][3] + b1v, 0.f));
        }
    }
    for (int i = tid; i < HH * 28; i += 512) w2s[i] = __ldg(&w2[i]);
    __syncthreads();

    #pragma unroll
    for (int rr = 0; rr < 8; rr++) {
        int row = warp * 8 + rr;
        int grow = brow + row;
        if (grow >= NN || lane >= 28) continue;
        const float* zr = zs + (size_t)row * ZROW;
        float a = 0.f;
        #pragma unroll 8
        for (int k = 0; k < HH; k++) a = fmaf(zr[k], w2s[k * 28 + lane], a);
        out[(size_t)grow * 28 + lane] = a + __ldg(&b2[lane]);
    }
}

// ------- virtual node v2: 32 graphs/block, smem weight tiles ----------------
#define VG 32
#define VROW 260
#define SMEM_V ((VG * VROW + 64 * HH) * 4)

__global__ void __launch_bounds__(256)
k_vn(const float* __restrict__ w, const float* __restrict__ bias,
     const float* __restrict__ lng, const float* __restrict__ lnb) {
    extern __shared__ __align__(16) float vsm[];
    float* vnin = vsm;
    float* wt   = vsm + VG * VROW;
    int tid = threadIdx.x;
    int g0 = blockIdx.x * VG;

    for (int i = tid; i < VG * HH; i += 256) {
        int g = i >> 8, c = i & 255;
        int gid = g0 + g;
        float v = 0.f;
        if (gid < NG) {
            v = g_vnagg[(size_t)gid * HH + c] + g_vn[(size_t)gid * HH + c];
            g_vnagg[(size_t)gid * HH + c] = 0.f;
        }
        vnin[g * VROW + c] = v;
    }

    int gl = tid >> 3, sub = tid & 7;
    float acc[32];
    #pragma unroll
    for (int j = 0; j < 32; j++) acc[j] = 0.f;

    for (int kt = 0; kt < 4; kt++) {
        __syncthreads();
        for (int v4 = tid; v4 < 4096; v4 += 256) {
            int k = v4 >> 6, c4 = v4 & 63;
            ((float4*)wt)[k * 64 + c4] = ((const float4*)w)[(size_t)(kt * 64 + k) * 64 + c4];
        }
        __syncthreads();
        for (int k = 0; k < 64; k++) {
            float xv = vnin[gl * VROW + kt * 64 + k];
            const float* wr = wt + k * 256 + sub;
            #pragma unroll
            for (int j = 0; j < 32; j++) acc[j] = fmaf(xv, wr[8 * j], acc[j]);
        }
    }

    float s = 0.f, ss = 0.f;
    float y[32];
    #pragma unroll
    for (int j = 0; j < 32; j++) {
        y[j] = acc[j] + __ldg(&bias[sub + 8 * j]);
        s += y[j]; ss += y[j] * y[j];
    }
    #pragma unroll
    for (int o = 1; o < 8; o <<= 1) {
        s  += __shfl_xor_sync(0xffffffffu, s,  o);
        ss += __shfl_xor_sync(0xffffffffu, ss, o);
    }
    float mean = s * (1.f / HH);
    float var  = ss * (1.f / HH) - mean * mean;
    float rstd = rsqrtf(var + 1e-5f);
    int gid = g0 + gl;
    if (gid < NG) {
        #pragma unroll
        for (int j = 0; j < 32; j++) {
            int col = sub + 8 * j;
            float z = (y[j] - mean) * rstd * __ldg(&lng[col]) + __ldg(&lnb[col]);
            g_vn[(size_t)gid * HH + col] = fmaxf(z, 0.f);
        }
    }
}

// ---------------------------------------------------------------------------
extern "C" void kernel_launch(void* const* d_in, const int* in_sizes, int n_in,
                              void* d_out, int out_size) {
    const int*   x     = (const int*)  d_in[0];
    const int*   ei    = (const int*)  d_in[1];
    const int*   ea    = (const int*)  d_in[2];
    const int*   batch = (const int*)  d_in[3];
    const float* aemb  = (const float*)d_in[4];
    const float* bemb  = (const float*)d_in[5];
    const float* vn0   = (const float*)d_in[6];
    const float* w1    = (const float*)d_in[7];
    const float* b1    = (const float*)d_in[8];
    const float* w2    = (const float*)d_in[9];
    const float* b2    = (const float*)d_in[10];
    const float* eps   = (const float*)d_in[11];
    const float* lng   = (const float*)d_in[12];
    const float* lnb   = (const float*)d_in[13];
    const float* vnw   = (const float*)d_in[14];
    const float* vnb   = (const float*)d_in[15];
    const float* vlg   = (const float*)d_in[16];
    const float* vlb   = (const float*)d_in[17];
    const float* hw1   = (const float*)d_in[18];
    const float* hb1   = (const float*)d_in[19];
    const float* hw2   = (const float*)d_in[20];
    const float* hb2   = (const float*)d_in[21];
    float* out = (float*)d_out;

    float *p_vn;
    cudaGetSymbolAddress((void**)&p_vn, g_vn);
    __nv_bfloat16 *w1h, *w1l, *w2h, *w2l, *hwh, *hwl;
    cudaGetSymbolAddress((void**)&w1h, g_w1t_hi);
    cudaGetSymbolAddress((void**)&w1l, g_w1t_lo);
    cudaGetSymbolAddress((void**)&w2h, g_w2t_hi);
    cudaGetSymbolAddress((void**)&w2l, g_w2t_lo);
    cudaGetSymbolAddress((void**)&hwh, g_hw1t_hi);
    cudaGetSymbolAddress((void**)&hwl, g_hw1t_lo);

    cudaFuncSetAttribute(k_layer, cudaFuncAttributeMaxDynamicSharedMemorySize, SMEM_L);
    cudaFuncSetAttribute(k_head,  cudaFuncAttributeMaxDynamicSharedMemorySize, SMEM_H);
    cudaFuncSetAttribute(k_vn,    cudaFuncAttributeMaxDynamicSharedMemorySize, SMEM_V);

    const int nb_nh = (NN * H4 + 255) / 256;
    const int ggrid = NNP / 128;

    k_prep<<<(NL * HH * HH + 255) / 256, 256>>>(w1, w1h, w1l, HH, HH, NL);
    k_prep<<<(NL * HH * HH + 255) / 256, 256>>>(w2, w2h, w2l, HH, HH, NL);
    k_prep<<<(JKD * HH + 255) / 256, 256>>>(hw1, hwh, hwl, JKD, HH, 1);

    k_embed<<<nb_nh, 256>>>(x, aemb, vn0);
    k_hist<<<(NE + 255) / 256, 256>>>(ei);
    k_scan1<<<NBLK, 256>>>();
    k_scan2<<<1, 256>>>();
    k_scan3<<<NBLK, 256>>>();
    k_fill<<<(NE + 255) / 256, 256>>>(ei, ea, batch);

    for (int l = 0; l < NL; l++) {
        k_agg<<<(NN + 7) / 8, 256>>>(bemb, batch, eps, l);
        k_layer<<<ggrid, 512, SMEM_L>>>(
            batch, p_vn, l,
            w1h + (size_t)l * HH * HH, w1l + (size_t)l * HH * HH, b1 + l * HH,
            w2h + (size_t)l * HH * HH, w2l + (size_t)l * HH * HH, b2 + l * HH,
            lng + l * HH, lnb + l * HH);
        k_vn<<<(NG + VG - 1) / VG, 256, SMEM_V>>>(
            vnw + (size_t)l * HH * HH, vnb + l * HH, vlg + l * HH, vlb + l * HH);
    }

    k_head<<<ggrid, 512, SMEM_H>>>(hwh, hwl, hb1, hw2, hb2, out);
}

// round 16
// speedup vs baseline: 1.1600x; 1.0759x over previous
#include <cuda_runtime.h>
#include <cuda_bf16.h>
#include <cstdint>

#define NN  150000
#define NNP 150016
#define NE  450000
#define NG  5000
#define HH  256
#define H4  64
#define JKD 1536
#define NL  5
#define NBLK 147

// ---------------- scratch ---------------------------------------------------
__device__ float g_jk   [NNP * JKD];
__device__ float g_vn   [NG * HH];
__device__ float g_vnagg[NG * HH];
__device__ __nv_bfloat16 g_ah[NNP * HH];
__device__ __nv_bfloat16 g_al[NNP * HH];
__device__ int g_deg [NN];
__device__ int g_off [NN + 1];
__device__ int g_cur [NN];
__device__ int g_esrc[NE];
__device__ int g_emet[NE];
__device__ int g_bsum[256];
__device__ __nv_bfloat16 g_w1t_hi[NL * HH * HH];
__device__ __nv_bfloat16 g_w1t_lo[NL * HH * HH];
__device__ __nv_bfloat16 g_w2t_hi[NL * HH * HH];
__device__ __nv_bfloat16 g_w2t_lo[NL * HH * HH];
__device__ __nv_bfloat16 g_hw1t_hi[HH * JKD];
__device__ __nv_bfloat16 g_hw1t_lo[HH * JKD];

static __device__ __forceinline__ float4 f4zero() { return make_float4(0.f,0.f,0.f,0.f); }

static __device__ __forceinline__ uint32_t smem_u32(const void* p) {
    uint32_t a;
    asm("{ .reg .u64 t; cvta.to.shared.u64 t, %1; cvt.u32.u64 %0, t; }" : "=r"(a) : "l"(p));
    return a;
}
static __device__ __forceinline__ uint32_t pack_bf(float lo, float hi) {
    uint32_t d;
    asm("cvt.rn.bf16x2.f32 %0, %1, %2;" : "=r"(d) : "f"(hi), "f"(lo));
    return d;
}
static __device__ __forceinline__ void redv4(float* p, float a, float b, float c, float d) {
    asm volatile("red.global.add.v4.f32 [%0], {%1,%2,%3,%4};"
                 :: "l"(p), "f"(a), "f"(b), "f"(c), "f"(d) : "memory");
}
static __device__ __forceinline__ void ldmx4(uint32_t r[4], uint32_t addr) {
    asm volatile("ldmatrix.sync.aligned.m8n8.x4.shared.b16 {%0,%1,%2,%3}, [%4];"
                 : "=r"(r[0]), "=r"(r[1]), "=r"(r[2]), "=r"(r[3]) : "r"(addr));
}
static __device__ __forceinline__ void mma_bf(float c[4], const uint32_t a[4],
                                              uint32_t b0, uint32_t b1) {
    asm volatile("mma.sync.aligned.m16n8k16.row.col.f32.bf16.bf16.f32 "
                 "{%0,%1,%2,%3},{%4,%5,%6,%7},{%8,%9},{%0,%1,%2,%3};"
                 : "+f"(c[0]), "+f"(c[1]), "+f"(c[2]), "+f"(c[3])
                 : "r"(a[0]), "r"(a[1]), "r"(a[2]), "r"(a[3]), "r"(b0), "r"(b1));
}
static __device__ __forceinline__ void cpasync16(uint32_t dst, const void* src) {
    asm volatile("cp.async.cg.shared.global [%0], [%1], 16;" :: "r"(dst), "l"(src));
}
#define CP_COMMIT() asm volatile("cp.async.commit_group;" ::: "memory")
#define CP_WAIT1()  asm volatile("cp.async.wait_group 1;" ::: "memory")
#define CP_WAIT0()  asm volatile("cp.async.wait_group 0;" ::: "memory")

// ---------------- weight prep -----------------------------------------------
__global__ void k_prep(const float* __restrict__ src, __nv_bfloat16* __restrict__ dhi,
                       __nv_bfloat16* __restrict__ dlo, int K, int N, int nmat) {
    int e = blockIdx.x * blockDim.x + threadIdx.x;
    if (e >= nmat * K * N) return;
    int m = e / (K * N), rem = e % (K * N);
    int n = rem / K, k = rem % K;
    float v = src[(size_t)m * K * N + (size_t)k * N + n];
    __nv_bfloat16 h = __float2bfloat16(v);
    __nv_bfloat16 l = __float2bfloat16(v - __bfloat162float(h));
    size_t o = (size_t)m * K * N + (size_t)n * K + k;
    dhi[o] = h; dlo[o] = l;
}

// ---------------- embed -----------------------------------------------------
__global__ void k_embed(const int* __restrict__ x,
                        const float* __restrict__ atom_emb,
                        const float* __restrict__ vn0) {
    int i = blockIdx.x * blockDim.x + threadIdx.x;
    if (i < NG * H4) {
        ((float4*)g_vnagg)[i] = f4zero();
        ((float4*)g_vn)[i] = ((const float4*)vn0)[i & (H4 - 1)];
    }
    if (i < NN) g_deg[i] = 0;
    if (i >= NN * H4) return;
    int n = i >> 6, c4 = i & 63;
    float4 v = ((const float4*)atom_emb)[x[n] * H4 + c4];
    ((float4*)g_jk)[(size_t)n * (JKD / 4) + c4] = v;
}

// ---------------- CSR build --------------------------------------------------
__global__ void k_hist(const int* __restrict__ ei) {
    int e = blockIdx.x * blockDim.x + threadIdx.x;
    if (e < NE) atomicAdd(&g_deg[ei[NE + e]], 1);
}
__global__ void k_scan1() {
    __shared__ int wsum[8];
    int b = blockIdx.x, tid = threadIdx.x;
    int lane = tid & 31, w = tid >> 5;
    int idx = b * 1024 + tid * 4;
    int4 v = make_int4(0, 0, 0, 0);
    if (idx + 3 < NN) v = *(const int4*)(g_deg + idx);
    else {
        if (idx + 0 < NN) v.x = g_deg[idx];
        if (idx + 1 < NN) v.y = g_deg[idx + 1];
        if (idx + 2 < NN) v.z = g_deg[idx + 2];
        if (idx + 3 < NN) v.w = g_deg[idx + 3];
    }
    int s = v.x + v.y + v.z + v.w;
    int t = s;
    #pragma unroll
    for (int o = 1; o < 32; o <<= 1) {
        int u = __shfl_up_sync(0xffffffffu, t, o);
        if (lane >= o) t += u;
    }
    if (lane == 31) wsum[w] = t;
    __syncthreads();
    if (w == 0 && lane < 8) {
        int u = wsum[lane];
        #pragma unroll
        for (int o = 1; o < 8; o <<= 1) {
            int x2 = __shfl_up_sync(0xffu, u, o);
            if (lane >= o) u += x2;
        }
        wsum[lane] = u;
    }
    __syncthreads();
    int excl = t - s + (w > 0 ? wsum[w - 1] : 0);
    if (idx     < NN) g_off[idx]     = excl;
    if (idx + 1 < NN) g_off[idx + 1] = excl + v.x;
    if (idx + 2 < NN) g_off[idx + 2] = excl + v.x + v.y;
    if (idx + 3 < NN) g_off[idx + 3] = excl + v.x + v.y + v.z;
    if (tid == 255) g_bsum[b] = excl + s;
}
__global__ void k_scan2() {
    __shared__ int wsum[8];
    int tid = threadIdx.x, lane = tid & 31, w = tid >> 5;
    int v = (tid < NBLK) ? g_bsum[tid] : 0;
    int t = v;
    #pragma unroll
    for (int o = 1; o < 32; o <<= 1) {
        int u = __shfl_up_sync(0xffffffffu, t, o);
        if (lane >= o) t += u;
    }
    if (lane == 31) wsum[w] = t;
    __syncthreads();
    if (w == 0 && lane < 8) {
        int u = wsum[lane];
        #pragma unroll
        for (int o = 1; o < 8; o <<= 1) {
            int x2 = __shfl_up_sync(0xffu, u, o);
            if (lane >= o) u += x2;
        }
        wsum[lane] = u;
    }
    __syncthreads();
    int excl = t - v + (w > 0 ? wsum[w - 1] : 0);
    if (tid < NBLK) g_bsum[tid] = excl;
}
__global__ void k_scan3() {
    int add = g_bsum[blockIdx.x];
    int idx = blockIdx.x * 1024 + threadIdx.x * 4;
    #pragma unroll
    for (int j = 0; j < 4; j++) {
        if (idx + j < NN) {
            int o = g_off[idx + j] + add;
            g_off[idx + j] = o;
            g_cur[idx + j] = o;
        }
    }
    if (blockIdx.x == 0 && threadIdx.x == 0) g_off[NN] = NE;
}
__global__ void k_fill(const int* __restrict__ ei, const int* __restrict__ ea,
                       const int* __restrict__ batch) {
    int e = blockIdx.x * blockDim.x + threadIdx.x;
    if (e >= NE) return;
    int src = ei[e], dst = ei[NE + e];
    int pos = atomicAdd(&g_cur[dst], 1);
    g_esrc[pos] = src;
    g_emet[pos] = ea[e] | (batch[src] << 2);
}

// ------- gather + GINE combine + bf16 split -> A planes ---------------------
// l==0: h rows come from atom_emb[x[*]] (bit-identical to jk slice 0, cached)
__global__ void __launch_bounds__(256)
k_agg(const float* __restrict__ bond, const int* __restrict__ batch,
      const float* __restrict__ eps, int l,
      const int* __restrict__ x, const float* __restrict__ aemb) {
    int warp = threadIdx.x >> 5, lane = threadIdx.x & 31;
    int node = blockIdx.x * 8 + warp;
    if (node >= NN) return;
    int beg = g_off[node], end = g_off[node + 1];
    float4 a0 = f4zero(), a1 = f4zero();
    const float* hb = g_jk + (size_t)l * HH + lane * 8;
    const float* ab = aemb + lane * 8;
    const float* vb = g_vn + lane * 8;
    const float* bb = bond + lane * 8;
    for (int base = beg; base < end; base += 32) {
        int n = end - base; if (n > 32) n = 32;
        int s = 0, m = 0;
        if (lane < n) { s = g_esrc[base + lane]; m = g_emet[base + lane]; }
        for (int j = 0; j < n; j++) {
            int src = __shfl_sync(0xffffffffu, s, j);
            int mt  = __shfl_sync(0xffffffffu, m, j);
            const float* hp = (l == 0) ? (ab + (size_t)__ldg(&x[src]) * HH)
                                       : (hb + (size_t)src * JKD);
            const float* vp = vb + (mt >> 2) * HH;
            const float* bp = bb + (mt & 3) * HH;
            float4 h0 = *(const float4*)hp, h1 = *(const float4*)(hp + 4);
            float4 v0 = *(const float4*)vp, v1 = *(const float4*)(vp + 4);
            float4 e0 = *(const float4*)bp, e1 = *(const float4*)(bp + 4);
            a0.x += fmaxf(h0.x + v0.x + e0.x, 0.f);
            a0.y += fmaxf(h0.y + v0.y + e0.y, 0.f);
            a0.z += fmaxf(h0.z + v0.z + e0.z, 0.f);
            a0.w += fmaxf(h0.w + v0.w + e0.w, 0.f);
            a1.x += fmaxf(h1.x + v1.x + e1.x, 0.f);
            a1.y += fmaxf(h1.y + v1.y + e1.y, 0.f);
            a1.z += fmaxf(h1.z + v1.z + e1.z, 0.f);
            a1.w += fmaxf(h1.w + v1.w + e1.w, 0.f);
        }
    }
    const float alpha = 1.f + __ldg(&eps[l]);
    const float* hp2 = (l == 0) ? (ab + (size_t)__ldg(&x[node]) * HH)
                                : (g_jk + (size_t)node * JKD + (size_t)l * HH + lane * 8);
    const float* vp2 = g_vn + (size_t)__ldg(&batch[node]) * HH + lane * 8;
    float4 h0 = *(const float4*)hp2, h1 = *(const float4*)(hp2 + 4);
    float4 v0 = *(const float4*)vp2, v1 = *(const float4*)(vp2 + 4);
    float f[8];
    f[0] = fmaf(alpha, h0.x + v0.x, a0.x);
    f[1] = fmaf(alpha, h0.y + v0.y, a0.y);
    f[2] = fmaf(alpha, h0.z + v0.z, a0.z);
    f[3] = fmaf(alpha, h0.w + v0.w, a0.w);
    f[4] = fmaf(alpha, h1.x + v1.x, a1.x);
    f[5] = fmaf(alpha, h1.y + v1.y, a1.y);
    f[6] = fmaf(alpha, h1.z + v1.z, a1.z);
    f[7] = fmaf(alpha, h1.w + v1.w, a1.w);
    uint32_t hi[4], lo[4];
    #pragma unroll
    for (int q = 0; q < 4; q++) {
        float f0 = f[2*q], f1 = f[2*q+1];
        __nv_bfloat16 b0 = __float2bfloat16(f0), b1 = __float2bfloat16(f1);
        hi[q] = ((uint32_t)__bfloat16_as_ushort(b1) << 16) | __bfloat16_as_ushort(b0);
        lo[q] = pack_bf(f0 - __bfloat162float(b0), f1 - __bfloat162float(b1));
    }
    ((uint4*)(g_ah + (size_t)node * HH))[lane] = make_uint4(hi[0], hi[1], hi[2], hi[3]);
    ((uint4*)(g_al + (size_t)node * HH))[lane] = make_uint4(lo[0], lo[1], lo[2], lo[3]);
}

// ===================== fused layer megakernel (R11 best config) =============
#define ROWB   80
#define A_SZ   (128 * ROWB)
#define B_SZ   (256 * ROWB)
#define STG    (2 * A_SZ + 2 * B_SZ) // 61440 (Ah|Al|Bh|Bl)
#define TROW   528
#define TP_SZ  (128 * TROW)
#define B2_OFF (2 * TP_SZ)           // 135168
#define ROW2B  48
#define B2P_SZ (256 * ROW2B)         // 12288 per plane
#define B2_STG2 (2 * B2P_SZ)         // 24576 per stage, 3 stages
#define SMEM_L (B2_OFF + 3 * B2_STG2) // 208896
#define SMEM_H (3 * STG)              // 184320
#define ZROW   260

__global__ void __launch_bounds__(512, 1)
k_layer(const int* __restrict__ batch, const float* __restrict__ vn, int layer,
        const __nv_bfloat16* __restrict__ B1h, const __nv_bfloat16* __restrict__ B1l,
        const float* __restrict__ bias1,
        const __nv_bfloat16* __restrict__ B2h, const __nv_bfloat16* __restrict__ B2l,
        const float* __restrict__ bias2,
        const float* __restrict__ lng, const float* __restrict__ lnb, int last) {
    extern __shared__ __align__(128) char smem[];
    const int tid = threadIdx.x, warp = tid >> 5, lane = tid & 31;
    const int brow = blockIdx.x * 128;
    const int wm = warp & 3, wn = warp >> 2;
    const uint32_t sb = smem_u32(smem);

    const int ar = tid >> 2, aq = tid & 3;
    const __nv_bfloat16* Ahp = g_ah + (size_t)(brow + ar) * HH + aq * 8;
    const __nv_bfloat16* Alp = g_al + (size_t)(brow + ar) * HH + aq * 8;
    const int bplane = tid >> 8, brw = tid & 255;
    const __nv_bfloat16* B1p = (bplane ? B1l : B1h) + (size_t)brw * HH;
    const __nv_bfloat16* B2p = (bplane ? B2l : B2h) + (size_t)brw * HH;

    const uint32_t a1_addr = sb + (uint32_t)(wm * 32 + (lane & 15)) * ROWB + (lane >> 4) * 16;
    const int bn = wn * 64 + (lane & 7) + ((lane >> 4) << 3);
    const uint32_t b1_addr = sb + 2 * A_SZ + (uint32_t)bn * ROWB + ((lane >> 3) & 1) * 16;
    const uint32_t a2_addr = sb + (uint32_t)(wm * 32 + (lane & 15)) * TROW + (lane >> 4) * 16;
    const uint32_t b2_addr = sb + B2_OFF + (uint32_t)bn * ROW2B + ((lane >> 3) & 1) * 16;

    float acc[2][8][4];
    #pragma unroll
    for (int mi = 0; mi < 2; mi++)
        #pragma unroll
        for (int ni = 0; ni < 8; ni++)
            #pragma unroll
            for (int j = 0; j < 4; j++) acc[mi][ni][j] = 0.f;

    auto issueP1 = [&](int c) {
        uint32_t base = sb + (uint32_t)(c % 3) * STG;
        uint32_t adst = base + (uint32_t)ar * ROWB + aq * 16;
        cpasync16(adst,        Ahp + c * 32);
        cpasync16(adst + A_SZ, Alp + c * 32);
        uint32_t bdst = base + 2 * A_SZ + bplane * B_SZ + brw * ROWB;
        const char* bsrc = (const char*)(B1p + c * 32);
        #pragma unroll
        for (int j = 0; j < 4; j++) cpasync16(bdst + j * 16, bsrc + j * 16);
        CP_COMMIT();
    };
    auto issueB2 = [&](int c) {
        uint32_t bdst = sb + B2_OFF + (uint32_t)(c % 3) * B2_STG2 + bplane * B2P_SZ + brw * ROW2B;
        const char* bsrc = (const char*)(B2p + c * 16);
        cpasync16(bdst,      bsrc);
        cpasync16(bdst + 16, bsrc + 16);
        CP_COMMIT();
    };
    auto mma_block1 = [&](uint32_t aBase, uint32_t bBase) {
        #pragma unroll
        for (int k16 = 0; k16 < 2; k16++) {
            uint32_t ah[2][4], al[2][4];
            #pragma unroll
            for (int mi = 0; mi < 2; mi++) {
                uint32_t aa = aBase + mi * 16 * ROWB + k16 * 32;
                ldmx4(ah[mi], aa);
                ldmx4(al[mi], aa + A_SZ);
            }
            #pragma unroll
            for (int np = 0; np < 4; np++) {
                uint32_t ba = bBase + np * 16 * ROWB + k16 * 32;
                uint32_t bh[4], bl[4];
                ldmx4(bh, ba);
                ldmx4(bl, ba + B_SZ);
                #pragma unroll
                for (int g = 0; g < 2; g++) {
                    #pragma unroll
                    for (int mi = 0; mi < 2; mi++) {
                        float* cc = acc[mi][np * 2 + g];
                        mma_bf(cc, ah[mi], bh[2*g], bh[2*g+1]);
                        mma_bf(cc, ah[mi], bl[2*g], bl[2*g+1]);
                        mma_bf(cc, al[mi], bh[2*g], bh[2*g+1]);
                    }
                }
            }
        }
    };

    // ---------------- phase 1: GEMM1 (3-stage ring, 1 sync/chunk) ----------
    issueP1(0); issueP1(1);
    #pragma unroll
    for (int c = 0; c < 8; c++) {
        if (c + 1 < 8) { CP_WAIT1(); } else { CP_WAIT0(); }
        __syncthreads();
        if (c + 2 < 8) issueP1(c + 2);
        uint32_t so = (uint32_t)(c % 3) * STG;
        mma_block1(a1_addr + so, b1_addr + so);
    }
    __syncthreads();

    // early B2 prefetch (overlaps t writeback)
    issueB2(0); issueB2(1);

    // ---------------- t -> smem bf16 planes (bias + relu + split) ---------
    #pragma unroll
    for (int mi = 0; mi < 2; mi++) {
        int r = wm * 32 + mi * 16 + (lane >> 2);
        #pragma unroll
        for (int ni = 0; ni < 8; ni++) {
            int col = wn * 64 + ni * 8 + (lane & 3) * 2;
            float b0 = __ldg(&bias1[col]), b1v = __ldg(&bias1[col + 1]);
            float v0 = fmaxf(acc[mi][ni][0] + b0, 0.f);
            float v1 = fmaxf(acc[mi][ni][1] + b1v, 0.f);
            float v2 = fmaxf(acc[mi][ni][2] + b0, 0.f);
            float v3 = fmaxf(acc[mi][ni][3] + b1v, 0.f);
            __nv_bfloat16 h0 = __float2bfloat16(v0), h1 = __float2bfloat16(v1);
            __nv_bfloat16 h2 = __float2bfloat16(v2), h3 = __float2bfloat16(v3);
            uint32_t off0 = (uint32_t)r * TROW + col * 2;
            uint32_t off1 = (uint32_t)(r + 8) * TROW + col * 2;
            *(uint32_t*)(smem + off0) = ((uint32_t)__bfloat16_as_ushort(h1) << 16) | __bfloat16_as_ushort(h0);
            *(uint32_t*)(smem + off1) = ((uint32_t)__bfloat16_as_ushort(h3) << 16) | __bfloat16_as_ushort(h2);
            *(uint32_t*)(smem + TP_SZ + off0) = pack_bf(v0 - __bfloat162float(h0), v1 - __bfloat162float(h1));
            *(uint32_t*)(smem + TP_SZ + off1) = pack_bf(v2 - __bfloat162float(h2), v3 - __bfloat162float(h3));
        }
    }

    #pragma unroll
    for (int mi = 0; mi < 2; mi++)
        #pragma unroll
        for (int ni = 0; ni < 8; ni++)
            #pragma unroll
            for (int j = 0; j < 4; j++) acc[mi][ni][j] = 0.f;

    __syncthreads();

    // ---------------- phase 2: GEMM2 (16 k16-chunks, 3-stage ring) --------
    #pragma unroll
    for (int c = 0; c < 16; c++) {
        if (c + 1 < 16) { CP_WAIT1(); } else { CP_WAIT0(); }
        __syncthreads();
        if (c + 2 < 16) issueB2(c + 2);
        uint32_t ah[2][4], al[2][4];
        #pragma unroll
        for (int mi = 0; mi < 2; mi++) {
            uint32_t aa = a2_addr + mi * 16 * TROW + c * 32;
            ldmx4(ah[mi], aa);
            ldmx4(al[mi], aa + TP_SZ);
        }
        uint32_t bbase = b2_addr + (uint32_t)(c % 3) * B2_STG2;
        #pragma unroll
        for (int np = 0; np < 4; np++) {
            uint32_t ba = bbase + np * 16 * ROW2B;
            uint32_t bh[4], bl[4];
            ldmx4(bh, ba);
            ldmx4(bl, ba + B2P_SZ);
            #pragma unroll
            for (int g = 0; g < 2; g++) {
                #pragma unroll
                for (int mi = 0; mi < 2; mi++) {
                    float* cc = acc[mi][np * 2 + g];
                    mma_bf(cc, ah[mi], bh[2*g], bh[2*g+1]);
                    mma_bf(cc, ah[mi], bl[2*g], bl[2*g+1]);
                    mma_bf(cc, al[mi], bh[2*g], bh[2*g+1]);
                }
            }
        }
    }
    __syncthreads();

    // ---------------- LN epilogue -----------------------------------------
    float* zs = (float*)smem;
    #pragma unroll
    for (int mi = 0; mi < 2; mi++) {
        int rl = wm * 32 + mi * 16 + (lane >> 2);
        #pragma unroll
        for (int ni = 0; ni < 8; ni++) {
            int col = wn * 64 + ni * 8 + (lane & 3) * 2;
            float b0 = __ldg(&bias2[col]), b1v = __ldg(&bias2[col + 1]);
            *(float2*)(zs + (size_t)rl * ZROW + col) =
                make_float2(acc[mi][ni][0] + b0, acc[mi][ni][1] + b1v);
            *(float2*)(zs + (size_t)(rl + 8) * ZROW + col) =
                make_float2(acc[mi][ni][2] + b0, acc[mi][ni][3] + b1v);
        }
    }
    __syncthreads();
    #pragma unroll
    for (int rr = 0; rr < 8; rr++) {
        int row = warp * 8 + rr;
        int grow = brow + row;
        float4 a4 = *(float4*)(zs + (size_t)row * ZROW + lane * 8);
        float4 b4 = *(float4*)(zs + (size_t)row * ZROW + lane * 8 + 4);
        float s  = a4.x + a4.y + a4.z + a4.w + b4.x + b4.y + b4.z + b4.w;
        float ss = a4.x*a4.x + a4.y*a4.y + a4.z*a4.z + a4.w*a4.w
                 + b4.x*b4.x + b4.y*b4.y + b4.z*b4.z + b4.w*b4.w;
        #pragma unroll
        for (int o = 16; o; o >>= 1) {
            s  += __shfl_xor_sync(0xffffffffu, s,  o);
            ss += __shfl_xor_sync(0xffffffffu, ss, o);
        }
        if (grow >= NN) continue;
        float mean = s * (1.f / HH);
        float var  = ss * (1.f / HH) - mean * mean;
        float rstd = rsqrtf(var + 1e-5f);
        float4 g0 = ((const float4*)lng)[lane * 2], g1 = ((const float4*)lng)[lane * 2 + 1];
        float4 c0 = ((const float4*)lnb)[lane * 2], c1 = ((const float4*)lnb)[lane * 2 + 1];
        const float4* hv = (const float4*)(g_jk + (size_t)grow * JKD + (size_t)layer * HH);
        int bidx = __ldg(&batch[grow]);
        const float4* vv = (const float4*)(vn + (size_t)bidx * HH);
        float4 h0 = hv[lane * 2], h1 = hv[lane * 2 + 1];
        float4 w0 = vv[lane * 2], w1 = vv[lane * 2 + 1];
        float4 o0, o1;
        o0.x = fmaxf((a4.x - mean) * rstd * g0.x + c0.x, 0.f) + h0.x + w0.x;
        o0.y = fmaxf((a4.y - mean) * rstd * g0.y + c0.y, 0.f) + h0.y + w0.y;
        o0.z = fmaxf((a4.z - mean) * rstd * g0.z + c0.z, 0.f) + h0.z + w0.z;
        o0.w = fmaxf((a4.w - mean) * rstd * g0.w + c0.w, 0.f) + h0.w + w0.w;
        o1.x = fmaxf((b4.x - mean) * rstd * g1.x + c1.x, 0.f) + h1.x + w1.x;
        o1.y = fmaxf((b4.y - mean) * rstd * g1.y + c1.y, 0.f) + h1.y + w1.y;
        o1.z = fmaxf((b4.z - mean) * rstd * g1.z + c1.z, 0.f) + h1.z + w1.z;
        o1.w = fmaxf((b4.w - mean) * rstd * g1.w + c1.w, 0.f) + h1.w + w1.w;
        float4* jkp = (float4*)(g_jk + (size_t)grow * JKD + (size_t)(layer + 1) * HH);
        jkp[lane * 2]     = o0;
        jkp[lane * 2 + 1] = o1;
        if (!last) {
            float* va = g_vnagg + (size_t)bidx * HH + lane * 8;
            redv4(va,     o0.x, o0.y, o0.z, o0.w);
            redv4(va + 4, o1.x, o1.y, o1.z, o1.w);
        }
    }
}

// ---- head: t = relu(jk @ hw1 + hb1); out = t @ hw2 + hb2 (fused) -----------
__global__ void __launch_bounds__(512, 1)
k_head(const __nv_bfloat16* __restrict__ Bh, const __nv_bfloat16* __restrict__ Bl,
       const float* __restrict__ bias1,
       const float* __restrict__ w2, const float* __restrict__ b2,
       float* __restrict__ out) {
    extern __shared__ __align__(128) char smem[];
    const int tid = threadIdx.x, warp = tid >> 5, lane = tid & 31;
    const int brow = blockIdx.x * 128;
    const int wm = warp & 3, wn = warp >> 2;
    const uint32_t sb = smem_u32(smem);
    const int nch = JKD / 32;   // 48

    const int ar = tid >> 2, aq = tid & 3;
    const float* Ap = g_jk + (size_t)(brow + ar) * JKD + aq * 8;
    const int bplane = tid >> 8, brw = tid & 255;
    const __nv_bfloat16* Bp = (bplane ? Bl : Bh) + (size_t)brw * JKD;

    const uint32_t a_addr = sb + (uint32_t)(wm * 32 + (lane & 15)) * ROWB + (lane >> 4) * 16;
    const int bn = wn * 64 + (lane & 7) + ((lane >> 4) << 3);
    const uint32_t b_addr = sb + 2 * A_SZ + (uint32_t)bn * ROWB + ((lane >> 3) & 1) * 16;

    float acc[2][8][4];
    #pragma unroll
    for (int mi = 0; mi < 2; mi++)
        #pragma unroll
        for (int ni = 0; ni < 8; ni++)
            #pragma unroll
            for (int j = 0; j < 4; j++) acc[mi][ni][j] = 0.f;

    auto ldgA = [&](int c, float f[8]) {
        const float* ap = Ap + c * 32;
        *(float4*)(f)     = *(const float4*)(ap);
        *(float4*)(f + 4) = *(const float4*)(ap + 4);
    };
    auto stsA = [&](int c, const float f[8]) {
        uint32_t hi[4], lo[4];
        #pragma unroll
        for (int q = 0; q < 4; q++) {
            float f0 = f[2*q], f1 = f[2*q+1];
            __nv_bfloat16 h0 = __float2bfloat16(f0), h1 = __float2bfloat16(f1);
            hi[q] = ((uint32_t)__bfloat16_as_ushort(h1) << 16) | __bfloat16_as_ushort(h0);
            lo[q] = pack_bf(f0 - __bfloat162float(h0), f1 - __bfloat162float(h1));
        }
        char* p = smem + (c % 3) * STG + ar * ROWB + aq * 16;
        *(uint4*)(p)        = make_uint4(hi[0], hi[1], hi[2], hi[3]);
        *(uint4*)(p + A_SZ) = make_uint4(lo[0], lo[1], lo[2], lo[3]);
    };
    auto issueB = [&](int c) {
        uint32_t bdst = sb + (c % 3) * STG + 2 * A_SZ + bplane * B_SZ + brw * ROWB;
        const char* bsrc = (const char*)(Bp + c * 32);
        #pragma unroll
        for (int j = 0; j < 4; j++) cpasync16(bdst + j * 16, bsrc + j * 16);
        CP_COMMIT();
    };

    {
        float f0[8], f1[8];
        ldgA(0, f0); issueB(0); stsA(0, f0);
        ldgA(1, f1); issueB(1); stsA(1, f1);
        for (int c = 0; c < nch; c++) {
            if (c + 1 < nch) { CP_WAIT1(); } else { CP_WAIT0(); }
            __syncthreads();
            float fn[8];
            bool pre = (c + 2 < nch);
            if (pre) { ldgA(c + 2, fn); issueB(c + 2); }
            uint32_t so = (c % 3) * STG;
            #pragma unroll
            for (int k16 = 0; k16 < 2; k16++) {
                uint32_t ah[2][4], al[2][4];
                #pragma unroll
                for (int mi = 0; mi < 2; mi++) {
                    uint32_t aa = a_addr + so + mi * 16 * ROWB + k16 * 32;
                    ldmx4(ah[mi], aa);
                    ldmx4(al[mi], aa + A_SZ);
                }
                #pragma unroll
                for (int np = 0; np < 4; np++) {
                    uint32_t ba = b_addr + so + np * 16 * ROWB + k16 * 32;
                    uint32_t bh[4], bl[4];
                    ldmx4(bh, ba);
                    ldmx4(bl, ba + B_SZ);
                    #pragma unroll
                    for (int g = 0; g < 2; g++) {
                        #pragma unroll
                        for (int mi = 0; mi < 2; mi++) {
                            float* cc = acc[mi][np * 2 + g];
                            mma_bf(cc, ah[mi], bh[2*g], bh[2*g+1]);
                            mma_bf(cc, ah[mi], bl[2*g], bl[2*g+1]);
                            mma_bf(cc, al[mi], bh[2*g], bh[2*g+1]);
                        }
                    }
                }
            }
            if (pre) stsA(c + 2, fn);
        }
    }
    __syncthreads();

    // ---- fused head2: stage t=relu(acc+b1) and w2; out = t @ w2 + b2 -------
    float* zs = (float*)smem;
    float* w2s = zs + 128 * ZROW;
    #pragma unroll
    for (int mi = 0; mi < 2; mi++) {
        int rl = wm * 32 + mi * 16 + (lane >> 2);
        #pragma unroll
        for (int ni = 0; ni < 8; ni++) {
            int col = wn * 64 + ni * 8 + (lane & 3) * 2;
            float b0 = __ldg(&bias1[col]), b1v = __ldg(&bias1[col + 1]);
            *(float2*)(zs + (size_t)rl * ZROW + col) =
                make_float2(fmaxf(acc[mi][ni][0] + b0, 0.f), fmaxf(acc[mi][ni][1] + b1v, 0.f));
            *(float2*)(zs + (size_t)(rl + 8) * ZROW + col) =
                make_float2(fmaxf(acc[mi][ni][2] + b0, 0.f), fmaxf(acc[mi][ni][3] + b1v, 0.f));
        }
    }
    for (int i = tid; i < HH * 28; i += 512) w2s[i] = __ldg(&w2[i]);
    __syncthreads();

    #pragma unroll
    for (int rr = 0; rr < 8; rr++) {
        int row = warp * 8 + rr;
        int grow = brow + row;
        if (grow >= NN || lane >= 28) continue;
        const float* zr = zs + (size_t)row * ZROW;
        float a = 0.f;
        #pragma unroll 8
        for (int k = 0; k < HH; k++) a = fmaf(zr[k], w2s[k * 28 + lane], a);
        out[(size_t)grow * 28 + lane] = a + __ldg(&b2[lane]);
    }
}

// ------- virtual node v2: 32 graphs/block, smem weight tiles ----------------
#define VG 32
#define VROW 260
#define SMEM_V ((VG * VROW + 64 * HH) * 4)

__global__ void __launch_bounds__(256)
k_vn(const float* __restrict__ w, const float* __restrict__ bias,
     const float* __restrict__ lng, const float* __restrict__ lnb) {
    extern __shared__ __align__(16) float vsm[];
    float* vnin = vsm;
    float* wt   = vsm + VG * VROW;
    int tid = threadIdx.x;
    int g0 = blockIdx.x * VG;

    for (int i = tid; i < VG * HH; i += 256) {
        int g = i >> 8, c = i & 255;
        int gid = g0 + g;
        float v = 0.f;
        if (gid < NG) {
            v = g_vnagg[(size_t)gid * HH + c] + g_vn[(size_t)gid * HH + c];
            g_vnagg[(size_t)gid * HH + c] = 0.f;
        }
        vnin[g * VROW + c] = v;
    }

    int gl = tid >> 3, sub = tid & 7;
    float acc[32];
    #pragma unroll
    for (int j = 0; j < 32; j++) acc[j] = 0.f;

    for (int kt = 0; kt < 4; kt++) {
        __syncthreads();
        for (int v4 = tid; v4 < 4096; v4 += 256) {
            int k = v4 >> 6, c4 = v4 & 63;
            ((float4*)wt)[k * 64 + c4] = ((const float4*)w)[(size_t)(kt * 64 + k) * 64 + c4];
        }
        __syncthreads();
        for (int k = 0; k < 64; k++) {
            float xv = vnin[gl * VROW + kt * 64 + k];
            const float* wr = wt + k * 256 + sub;
            #pragma unroll
            for (int j = 0; j < 32; j++) acc[j] = fmaf(xv, wr[8 * j], acc[j]);
        }
    }

    float s = 0.f, ss = 0.f;
    float y[32];
    #pragma unroll
    for (int j = 0; j < 32; j++) {
        y[j] = acc[j] + __ldg(&bias[sub + 8 * j]);
        s += y[j]; ss += y[j] * y[j];
    }
    #pragma unroll
    for (int o = 1; o < 8; o <<= 1) {
        s  += __shfl_xor_sync(0xffffffffu, s,  o);
        ss += __shfl_xor_sync(0xffffffffu, ss, o);
    }
    float mean = s * (1.f / HH);
    float var  = ss * (1.f / HH) - mean * mean;
    float rstd = rsqrtf(var + 1e-5f);
    int gid = g0 + gl;
    if (gid < NG) {
        #pragma unroll
        for (int j = 0; j < 32; j++) {
            int col = sub + 8 * j;
            float z = (y[j] - mean) * rstd * __ldg(&lng[col]) + __ldg(&lnb[col]);
            g_vn[(size_t)gid * HH + col] = fmaxf(z, 0.f);
        }
    }
}

// ---------------------------------------------------------------------------
extern "C" void kernel_launch(void* const* d_in, const int* in_sizes, int n_in,
                              void* d_out, int out_size) {
    const int*   x     = (const int*)  d_in[0];
    const int*   ei    = (const int*)  d_in[1];
    const int*   ea    = (const int*)  d_in[2];
    const int*   batch = (const int*)  d_in[3];
    const float* aemb  = (const float*)d_in[4];
    const float* bemb  = (const float*)d_in[5];
    const float* vn0   = (const float*)d_in[6];
    const float* w1    = (const float*)d_in[7];
    const float* b1    = (const float*)d_in[8];
    const float* w2    = (const float*)d_in[9];
    const float* b2    = (const float*)d_in[10];
    const float* eps   = (const float*)d_in[11];
    const float* lng   = (const float*)d_in[12];
    const float* lnb   = (const float*)d_in[13];
    const float* vnw   = (const float*)d_in[14];
    const float* vnb   = (const float*)d_in[15];
    const float* vlg   = (const float*)d_in[16];
    const float* vlb   = (const float*)d_in[17];
    const float* hw1   = (const float*)d_in[18];
    const float* hb1   = (const float*)d_in[19];
    const float* hw2   = (const float*)d_in[20];
    const float* hb2   = (const float*)d_in[21];
    float* out = (float*)d_out;

    float *p_vn;
    cudaGetSymbolAddress((void**)&p_vn, g_vn);
    __nv_bfloat16 *w1h, *w1l, *w2h, *w2l, *hwh, *hwl;
    cudaGetSymbolAddress((void**)&w1h, g_w1t_hi);
    cudaGetSymbolAddress((void**)&w1l, g_w1t_lo);
    cudaGetSymbolAddress((void**)&w2h, g_w2t_hi);
    cudaGetSymbolAddress((void**)&w2l, g_w2t_lo);
    cudaGetSymbolAddress((void**)&hwh, g_hw1t_hi);
    cudaGetSymbolAddress((void**)&hwl, g_hw1t_lo);

    cudaFuncSetAttribute(k_layer, cudaFuncAttributeMaxDynamicSharedMemorySize, SMEM_L);
    cudaFuncSetAttribute(k_head,  cudaFuncAttributeMaxDynamicSharedMemorySize, SMEM_H);
    cudaFuncSetAttribute(k_vn,    cudaFuncAttributeMaxDynamicSharedMemorySize, SMEM_V);

    const int nb_nh = (NN * H4 + 255) / 256;
    const int ggrid = NNP / 128;

    k_prep<<<(NL * HH * HH + 255) / 256, 256>>>(w1, w1h, w1l, HH, HH, NL);
    k_prep<<<(NL * HH * HH + 255) / 256, 256>>>(w2, w2h, w2l, HH, HH, NL);
    k_prep<<<(JKD * HH + 255) / 256, 256>>>(hw1, hwh, hwl, JKD, HH, 1);

    k_embed<<<nb_nh, 256>>>(x, aemb, vn0);
    k_hist<<<(NE + 255) / 256, 256>>>(ei);
    k_scan1<<<NBLK, 256>>>();
    k_scan2<<<1, 256>>>();
    k_scan3<<<NBLK, 256>>>();
    k_fill<<<(NE + 255) / 256, 256>>>(ei, ea, batch);

    for (int l = 0; l < NL; l++) {
        k_agg<<<(NN + 7) / 8, 256>>>(bemb, batch, eps, l, x, aemb);
        k_layer<<<ggrid, 512, SMEM_L>>>(
            batch, p_vn, l,
            w1h + (size_t)l * HH * HH, w1l + (size_t)l * HH * HH, b1 + l * HH,
            w2h + (size_t)l * HH * HH, w2l + (size_t)l * HH * HH, b2 + l * HH,
            lng + l * HH, lnb + l * HH, l == NL - 1);
        if (l < NL - 1)
            k_vn<<<(NG + VG - 1) / VG, 256, SMEM_V>>>(
                vnw + (size_t)l * HH * HH, vnb + l * HH, vlg + l * HH, vlb + l * HH);
    }

    k_head<<<ggrid, 512, SMEM_H>>>(hwh, hwl, hb1, hw2, hb2, out);
}

// round 17
// speedup vs baseline: 1.2010x; 1.0353x over previous
#include <cuda_runtime.h>
#include <cuda_bf16.h>
#include <cstdint>

#define NN  150000
#define NNP 150016
#define NE  450000
#define NG  5000
#define HH  256
#define H4  64
#define JKD 1536
#define NL  5
#define NBLK 147

// ---------------- scratch ---------------------------------------------------
__device__ float g_jk   [NNP * JKD];
__device__ float g_vn   [NG * HH];
__device__ __nv_bfloat16 g_ah[NNP * HH];
__device__ __nv_bfloat16 g_al[NNP * HH];
__device__ int g_deg [NN];
__device__ int g_off [NN + 1];
__device__ int g_cur [NN];
__device__ int g_goff[NG + 1];
__device__ int g_esrc[NE];
__device__ int g_emet[NE];
__device__ int g_bsum[256];
__device__ __nv_bfloat16 g_w1t_hi[NL * HH * HH];
__device__ __nv_bfloat16 g_w1t_lo[NL * HH * HH];
__device__ __nv_bfloat16 g_w2t_hi[NL * HH * HH];
__device__ __nv_bfloat16 g_w2t_lo[NL * HH * HH];
__device__ __nv_bfloat16 g_hw1t_hi[HH * JKD];
__device__ __nv_bfloat16 g_hw1t_lo[HH * JKD];

static __device__ __forceinline__ float4 f4zero() { return make_float4(0.f,0.f,0.f,0.f); }

static __device__ __forceinline__ uint32_t smem_u32(const void* p) {
    uint32_t a;
    asm("{ .reg .u64 t; cvta.to.shared.u64 t, %1; cvt.u32.u64 %0, t; }" : "=r"(a) : "l"(p));
    return a;
}
static __device__ __forceinline__ uint32_t pack_bf(float lo, float hi) {
    uint32_t d;
    asm("cvt.rn.bf16x2.f32 %0, %1, %2;" : "=r"(d) : "f"(hi), "f"(lo));
    return d;
}
static __device__ __forceinline__ void ldmx4(uint32_t r[4], uint32_t addr) {
    asm volatile("ldmatrix.sync.aligned.m8n8.x4.shared.b16 {%0,%1,%2,%3}, [%4];"
                 : "=r"(r[0]), "=r"(r[1]), "=r"(r[2]), "=r"(r[3]) : "r"(addr));
}
static __device__ __forceinline__ void mma_bf(float c[4], const uint32_t a[4],
                                              uint32_t b0, uint32_t b1) {
    asm volatile("mma.sync.aligned.m16n8k16.row.col.f32.bf16.bf16.f32 "
                 "{%0,%1,%2,%3},{%4,%5,%6,%7},{%8,%9},{%0,%1,%2,%3};"
                 : "+f"(c[0]), "+f"(c[1]), "+f"(c[2]), "+f"(c[3])
                 : "r"(a[0]), "r"(a[1]), "r"(a[2]), "r"(a[3]), "r"(b0), "r"(b1));
}
static __device__ __forceinline__ void cpasync16(uint32_t dst, const void* src) {
    asm volatile("cp.async.cg.shared.global [%0], [%1], 16;" :: "r"(dst), "l"(src));
}
#define CP_COMMIT() asm volatile("cp.async.commit_group;" ::: "memory")
#define CP_WAIT1()  asm volatile("cp.async.wait_group 1;" ::: "memory")
#define CP_WAIT0()  asm volatile("cp.async.wait_group 0;" ::: "memory")

// ---------------- weight prep -----------------------------------------------
__global__ void k_prep(const float* __restrict__ src, __nv_bfloat16* __restrict__ dhi,
                       __nv_bfloat16* __restrict__ dlo, int K, int N, int nmat) {
    int e = blockIdx.x * blockDim.x + threadIdx.x;
    if (e >= nmat * K * N) return;
    int m = e / (K * N), rem = e % (K * N);
    int n = rem / K, k = rem % K;
    float v = src[(size_t)m * K * N + (size_t)k * N + n];
    __nv_bfloat16 h = __float2bfloat16(v);
    __nv_bfloat16 l = __float2bfloat16(v - __bfloat162float(h));
    size_t o = (size_t)m * K * N + (size_t)n * K + k;
    dhi[o] = h; dlo[o] = l;
}

// ---------------- embed -----------------------------------------------------
__global__ void k_embed(const int* __restrict__ x,
                        const float* __restrict__ atom_emb,
                        const float* __restrict__ vn0) {
    int i = blockIdx.x * blockDim.x + threadIdx.x;
    if (i < NG * H4)
        ((float4*)g_vn)[i] = ((const float4*)vn0)[i & (H4 - 1)];
    if (i < NN) g_deg[i] = 0;
    if (i >= NN * H4) return;
    int n = i >> 6, c4 = i & 63;
    float4 v = ((const float4*)atom_emb)[x[n] * H4 + c4];
    ((float4*)g_jk)[(size_t)n * (JKD / 4) + c4] = v;
}

// ---------------- CSR build --------------------------------------------------
__global__ void k_hist(const int* __restrict__ ei) {
    int e = blockIdx.x * blockDim.x + threadIdx.x;
    if (e < NE) atomicAdd(&g_deg[ei[NE + e]], 1);
}
__global__ void k_scan1() {
    __shared__ int wsum[8];
    int b = blockIdx.x, tid = threadIdx.x;
    int lane = tid & 31, w = tid >> 5;
    int idx = b * 1024 + tid * 4;
    int4 v = make_int4(0, 0, 0, 0);
    if (idx + 3 < NN) v = *(const int4*)(g_deg + idx);
    else {
        if (idx + 0 < NN) v.x = g_deg[idx];
        if (idx + 1 < NN) v.y = g_deg[idx + 1];
        if (idx + 2 < NN) v.z = g_deg[idx + 2];
        if (idx + 3 < NN) v.w = g_deg[idx + 3];
    }
    int s = v.x + v.y + v.z + v.w;
    int t = s;
    #pragma unroll
    for (int o = 1; o < 32; o <<= 1) {
        int u = __shfl_up_sync(0xffffffffu, t, o);
        if (lane >= o) t += u;
    }
    if (lane == 31) wsum[w] = t;
    __syncthreads();
    if (w == 0 && lane < 8) {
        int u = wsum[lane];
        #pragma unroll
        for (int o = 1; o < 8; o <<= 1) {
            int x2 = __shfl_up_sync(0xffu, u, o);
            if (lane >= o) u += x2;
        }
        wsum[lane] = u;
    }
    __syncthreads();
    int excl = t - s + (w > 0 ? wsum[w - 1] : 0);
    if (idx     < NN) g_off[idx]     = excl;
    if (idx + 1 < NN) g_off[idx + 1] = excl + v.x;
    if (idx + 2 < NN) g_off[idx + 2] = excl + v.x + v.y;
    if (idx + 3 < NN) g_off[idx + 3] = excl + v.x + v.y + v.z;
    if (tid == 255) g_bsum[b] = excl + s;
}
__global__ void k_scan2() {
    __shared__ int wsum[8];
    int tid = threadIdx.x, lane = tid & 31, w = tid >> 5;
    int v = (tid < NBLK) ? g_bsum[tid] : 0;
    int t = v;
    #pragma unroll
    for (int o = 1; o < 32; o <<= 1) {
        int u = __shfl_up_sync(0xffffffffu, t, o);
        if (lane >= o) t += u;
    }
    if (lane == 31) wsum[w] = t;
    __syncthreads();
    if (w == 0 && lane < 8) {
        int u = wsum[lane];
        #pragma unroll
        for (int o = 1; o < 8; o <<= 1) {
            int x2 = __shfl_up_sync(0xffu, u, o);
            if (lane >= o) u += x2;
        }
        wsum[lane] = u;
    }
    __syncthreads();
    int excl = t - v + (w > 0 ? wsum[w - 1] : 0);
    if (tid < NBLK) g_bsum[tid] = excl;
}
__global__ void k_scan3() {
    int add = g_bsum[blockIdx.x];
    int idx = blockIdx.x * 1024 + threadIdx.x * 4;
    #pragma unroll
    for (int j = 0; j < 4; j++) {
        if (idx + j < NN) {
            int o = g_off[idx + j] + add;
            g_off[idx + j] = o;
            g_cur[idx + j] = o;
        }
    }
    if (blockIdx.x == 0 && threadIdx.x == 0) g_off[NN] = NE;
}
__global__ void k_fill(const int* __restrict__ ei, const int* __restrict__ ea,
                       const int* __restrict__ batch) {
    int e = blockIdx.x * blockDim.x + threadIdx.x;
    if (e >= NE) return;
    int src = ei[e], dst = ei[NE + e];
    int pos = atomicAdd(&g_cur[dst], 1);
    g_esrc[pos] = src;
    g_emet[pos] = ea[e] | (batch[src] << 2);
}
// graph offsets from sorted batch
__global__ void k_goff(const int* __restrict__ batch) {
    int i = blockIdx.x * blockDim.x + threadIdx.x;
    if (i >= NN) return;
    int b = batch[i];
    int prev = (i == 0) ? -1 : batch[i - 1];
    for (int g = prev + 1; g <= b; g++) g_goff[g] = i;
    if (i == NN - 1)
        for (int g = b + 1; g <= NG; g++) g_goff[g] = NN;
}

// ------- gather + GINE combine + bf16 split -> A planes ---------------------
__global__ void __launch_bounds__(256)
k_agg(const float* __restrict__ bond, const int* __restrict__ batch,
      const float* __restrict__ eps, int l,
      const int* __restrict__ x, const float* __restrict__ aemb) {
    int warp = threadIdx.x >> 5, lane = threadIdx.x & 31;
    int node = blockIdx.x * 8 + warp;
    if (node >= NN) return;
    int beg = g_off[node], end = g_off[node + 1];
    float4 a0 = f4zero(), a1 = f4zero();
    const float* hb = g_jk + (size_t)l * HH + lane * 8;
    const float* ab = aemb + lane * 8;
    const float* vb = g_vn + lane * 8;
    const float* bb = bond + lane * 8;
    for (int base = beg; base < end; base += 32) {
        int n = end - base; if (n > 32) n = 32;
        int s = 0, m = 0;
        if (lane < n) { s = g_esrc[base + lane]; m = g_emet[base + lane]; }
        for (int j = 0; j < n; j++) {
            int src = __shfl_sync(0xffffffffu, s, j);
            int mt  = __shfl_sync(0xffffffffu, m, j);
            const float* hp = (l == 0) ? (ab + (size_t)__ldg(&x[src]) * HH)
                                       : (hb + (size_t)src * JKD);
            const float* vp = vb + (mt >> 2) * HH;
            const float* bp = bb + (mt & 3) * HH;
            float4 h0 = *(const float4*)hp, h1 = *(const float4*)(hp + 4);
            float4 v0 = *(const float4*)vp, v1 = *(const float4*)(vp + 4);
            float4 e0 = *(const float4*)bp, e1 = *(const float4*)(bp + 4);
            a0.x += fmaxf(h0.x + v0.x + e0.x, 0.f);
            a0.y += fmaxf(h0.y + v0.y + e0.y, 0.f);
            a0.z += fmaxf(h0.z + v0.z + e0.z, 0.f);
            a0.w += fmaxf(h0.w + v0.w + e0.w, 0.f);
            a1.x += fmaxf(h1.x + v1.x + e1.x, 0.f);
            a1.y += fmaxf(h1.y + v1.y + e1.y, 0.f);
            a1.z += fmaxf(h1.z + v1.z + e1.z, 0.f);
            a1.w += fmaxf(h1.w + v1.w + e1.w, 0.f);
        }
    }
    const float alpha = 1.f + __ldg(&eps[l]);
    const float* hp2 = (l == 0) ? (ab + (size_t)__ldg(&x[node]) * HH)
                                : (g_jk + (size_t)node * JKD + (size_t)l * HH + lane * 8);
    const float* vp2 = g_vn + (size_t)__ldg(&batch[node]) * HH + lane * 8;
    float4 h0 = *(const float4*)hp2, h1 = *(const float4*)(hp2 + 4);
    float4 v0 = *(const float4*)vp2, v1 = *(const float4*)(vp2 + 4);
    float f[8];
    f[0] = fmaf(alpha, h0.x + v0.x, a0.x);
    f[1] = fmaf(alpha, h0.y + v0.y, a0.y);
    f[2] = fmaf(alpha, h0.z + v0.z, a0.z);
    f[3] = fmaf(alpha, h0.w + v0.w, a0.w);
    f[4] = fmaf(alpha, h1.x + v1.x, a1.x);
    f[5] = fmaf(alpha, h1.y + v1.y, a1.y);
    f[6] = fmaf(alpha, h1.z + v1.z, a1.z);
    f[7] = fmaf(alpha, h1.w + v1.w, a1.w);
    uint32_t hi[4], lo[4];
    #pragma unroll
    for (int q = 0; q < 4; q++) {
        float f0 = f[2*q], f1 = f[2*q+1];
        __nv_bfloat16 b0 = __float2bfloat16(f0), b1 = __float2bfloat16(f1);
        hi[q] = ((uint32_t)__bfloat16_as_ushort(b1) << 16) | __bfloat16_as_ushort(b0);
        lo[q] = pack_bf(f0 - __bfloat162float(b0), f1 - __bfloat162float(b1));
    }
    ((uint4*)(g_ah + (size_t)node * HH))[lane] = make_uint4(hi[0], hi[1], hi[2], hi[3]);
    ((uint4*)(g_al + (size_t)node * HH))[lane] = make_uint4(lo[0], lo[1], lo[2], lo[3]);
}

// ===================== fused layer megakernel ===============================
#define ROWB   80
#define A_SZ   (128 * ROWB)
#define B_SZ   (256 * ROWB)
#define STG    (2 * A_SZ + 2 * B_SZ) // 61440
#define TROW   528
#define TP_SZ  (128 * TROW)
#define B2_OFF (2 * TP_SZ)
#define ROW2B  48
#define B2P_SZ (256 * ROW2B)
#define B2_STG2 (2 * B2P_SZ)
#define SMEM_L (B2_OFF + 3 * B2_STG2) // 208896
#define SMEM_H (3 * STG)              // 184320
#define ZROW   260

__global__ void __launch_bounds__(512, 1)
k_layer(const int* __restrict__ batch, const float* __restrict__ vn, int layer,
        const __nv_bfloat16* __restrict__ B1h, const __nv_bfloat16* __restrict__ B1l,
        const float* __restrict__ bias1,
        const __nv_bfloat16* __restrict__ B2h, const __nv_bfloat16* __restrict__ B2l,
        const float* __restrict__ bias2,
        const float* __restrict__ lng, const float* __restrict__ lnb) {
    extern __shared__ __align__(128) char smem[];
    const int tid = threadIdx.x, warp = tid >> 5, lane = tid & 31;
    const int brow = blockIdx.x * 128;
    const int wm = warp & 3, wn = warp >> 2;
    const uint32_t sb = smem_u32(smem);

    const int ar = tid >> 2, aq = tid & 3;
    const __nv_bfloat16* Ahp = g_ah + (size_t)(brow + ar) * HH + aq * 8;
    const __nv_bfloat16* Alp = g_al + (size_t)(brow + ar) * HH + aq * 8;
    const int bplane = tid >> 8, brw = tid & 255;
    const __nv_bfloat16* B1p = (bplane ? B1l : B1h) + (size_t)brw * HH;
    const __nv_bfloat16* B2p = (bplane ? B2l : B2h) + (size_t)brw * HH;

    const uint32_t a1_addr = sb + (uint32_t)(wm * 32 + (lane & 15)) * ROWB + (lane >> 4) * 16;
    const int bn = wn * 64 + (lane & 7) + ((lane >> 4) << 3);
    const uint32_t b1_addr = sb + 2 * A_SZ + (uint32_t)bn * ROWB + ((lane >> 3) & 1) * 16;
    const uint32_t a2_addr = sb + (uint32_t)(wm * 32 + (lane & 15)) * TROW + (lane >> 4) * 16;
    const uint32_t b2_addr = sb + B2_OFF + (uint32_t)bn * ROW2B + ((lane >> 3) & 1) * 16;

    float acc[2][8][4];
    #pragma unroll
    for (int mi = 0; mi < 2; mi++)
        #pragma unroll
        for (int ni = 0; ni < 8; ni++)
            #pragma unroll
            for (int j = 0; j < 4; j++) acc[mi][ni][j] = 0.f;

    auto issueP1 = [&](int c) {
        uint32_t base = sb + (uint32_t)(c % 3) * STG;
        uint32_t adst = base + (uint32_t)ar * ROWB + aq * 16;
        cpasync16(adst,        Ahp + c * 32);
        cpasync16(adst + A_SZ, Alp + c * 32);
        uint32_t bdst = base + 2 * A_SZ + bplane * B_SZ + brw * ROWB;
        const char* bsrc = (const char*)(B1p + c * 32);
        #pragma unroll
        for (int j = 0; j < 4; j++) cpasync16(bdst + j * 16, bsrc + j * 16);
        CP_COMMIT();
    };
    auto issueB2 = [&](int c) {
        uint32_t bdst = sb + B2_OFF + (uint32_t)(c % 3) * B2_STG2 + bplane * B2P_SZ + brw * ROW2B;
        const char* bsrc = (const char*)(B2p + c * 16);
        cpasync16(bdst,      bsrc);
        cpasync16(bdst + 16, bsrc + 16);
        CP_COMMIT();
    };
    auto mma_block1 = [&](uint32_t aBase, uint32_t bBase) {
        #pragma unroll
        for (int k16 = 0; k16 < 2; k16++) {
            uint32_t ah[2][4], al[2][4];
            #pragma unroll
            for (int mi = 0; mi < 2; mi++) {
                uint32_t aa = aBase + mi * 16 * ROWB + k16 * 32;
                ldmx4(ah[mi], aa);
                ldmx4(al[mi], aa + A_SZ);
            }
            #pragma unroll
            for (int np = 0; np < 4; np++) {
                uint32_t ba = bBase + np * 16 * ROWB + k16 * 32;
                uint32_t bh[4], bl[4];
                ldmx4(bh, ba);
                ldmx4(bl, ba + B_SZ);
                #pragma unroll
                for (int g = 0; g < 2; g++) {
                    #pragma unroll
                    for (int mi = 0; mi < 2; mi++) {
                        float* cc = acc[mi][np * 2 + g];
                        mma_bf(cc, ah[mi], bh[2*g], bh[2*g+1]);
                        mma_bf(cc, ah[mi], bl[2*g], bl[2*g+1]);
                        mma_bf(cc, al[mi], bh[2*g], bh[2*g+1]);
                    }
                }
            }
        }
    };

    // ---------------- phase 1: GEMM1 (3-stage ring) -------------------------
    issueP1(0); issueP1(1);
    #pragma unroll
    for (int c = 0; c < 8; c++) {
        if (c + 1 < 8) { CP_WAIT1(); } else { CP_WAIT0(); }
        __syncthreads();
        if (c + 2 < 8) issueP1(c + 2);
        uint32_t so = (uint32_t)(c % 3) * STG;
        mma_block1(a1_addr + so, b1_addr + so);
    }
    __syncthreads();

    issueB2(0); issueB2(1);

    // ---------------- t -> smem bf16 planes ---------------------------------
    #pragma unroll
    for (int mi = 0; mi < 2; mi++) {
        int r = wm * 32 + mi * 16 + (lane >> 2);
        #pragma unroll
        for (int ni = 0; ni < 8; ni++) {
            int col = wn * 64 + ni * 8 + (lane & 3) * 2;
            float b0 = __ldg(&bias1[col]), b1v = __ldg(&bias1[col + 1]);
            float v0 = fmaxf(acc[mi][ni][0] + b0, 0.f);
            float v1 = fmaxf(acc[mi][ni][1] + b1v, 0.f);
            float v2 = fmaxf(acc[mi][ni][2] + b0, 0.f);
            float v3 = fmaxf(acc[mi][ni][3] + b1v, 0.f);
            __nv_bfloat16 h0 = __float2bfloat16(v0), h1 = __float2bfloat16(v1);
            __nv_bfloat16 h2 = __float2bfloat16(v2), h3 = __float2bfloat16(v3);
            uint32_t off0 = (uint32_t)r * TROW + col * 2;
            uint32_t off1 = (uint32_t)(r + 8) * TROW + col * 2;
            *(uint32_t*)(smem + off0) = ((uint32_t)__bfloat16_as_ushort(h1) << 16) | __bfloat16_as_ushort(h0);
            *(uint32_t*)(smem + off1) = ((uint32_t)__bfloat16_as_ushort(h3) << 16) | __bfloat16_as_ushort(h2);
            *(uint32_t*)(smem + TP_SZ + off0) = pack_bf(v0 - __bfloat162float(h0), v1 - __bfloat162float(h1));
            *(uint32_t*)(smem + TP_SZ + off1) = pack_bf(v2 - __bfloat162float(h2), v3 - __bfloat162float(h3));
        }
    }

    #pragma unroll
    for (int mi = 0; mi < 2; mi++)
        #pragma unroll
        for (int ni = 0; ni < 8; ni++)
            #pragma unroll
            for (int j = 0; j < 4; j++) acc[mi][ni][j] = 0.f;

    __syncthreads();

    // ---------------- phase 2: GEMM2 ----------------------------------------
    #pragma unroll
    for (int c = 0; c < 16; c++) {
        if (c + 1 < 16) { CP_WAIT1(); } else { CP_WAIT0(); }
        __syncthreads();
        if (c + 2 < 16) issueB2(c + 2);
        uint32_t ah[2][4], al[2][4];
        #pragma unroll
        for (int mi = 0; mi < 2; mi++) {
            uint32_t aa = a2_addr + mi * 16 * TROW + c * 32;
            ldmx4(ah[mi], aa);
            ldmx4(al[mi], aa + TP_SZ);
        }
        uint32_t bbase = b2_addr + (uint32_t)(c % 3) * B2_STG2;
        #pragma unroll
        for (int np = 0; np < 4; np++) {
            uint32_t ba = bbase + np * 16 * ROW2B;
            uint32_t bh[4], bl[4];
            ldmx4(bh, ba);
            ldmx4(bl, ba + B2P_SZ);
            #pragma unroll
            for (int g = 0; g < 2; g++) {
                #pragma unroll
                for (int mi = 0; mi < 2; mi++) {
                    float* cc = acc[mi][np * 2 + g];
                    mma_bf(cc, ah[mi], bh[2*g], bh[2*g+1]);
                    mma_bf(cc, ah[mi], bl[2*g], bl[2*g+1]);
                    mma_bf(cc, al[mi], bh[2*g], bh[2*g+1]);
                }
            }
        }
    }
    __syncthreads();

    // ---------------- LN epilogue (no atomics) ------------------------------
    float* zs = (float*)smem;
    #pragma unroll
    for (int mi = 0; mi < 2; mi++) {
        int rl = wm * 32 + mi * 16 + (lane >> 2);
        #pragma unroll
        for (int ni = 0; ni < 8; ni++) {
            int col = wn * 64 + ni * 8 + (lane & 3) * 2;
            float b0 = __ldg(&bias2[col]), b1v = __ldg(&bias2[col + 1]);
            *(float2*)(zs + (size_t)rl * ZROW + col) =
                make_float2(acc[mi][ni][0] + b0, acc[mi][ni][1] + b1v);
            *(float2*)(zs + (size_t)(rl + 8) * ZROW + col) =
                make_float2(acc[mi][ni][2] + b0, acc[mi][ni][3] + b1v);
        }
    }
    __syncthreads();
    #pragma unroll
    for (int rr = 0; rr < 8; rr++) {
        int row = warp * 8 + rr;
        int grow = brow + row;
        float4 a4 = *(float4*)(zs + (size_t)row * ZROW + lane * 8);
        float4 b4 = *(float4*)(zs + (size_t)row * ZROW + lane * 8 + 4);
        float s  = a4.x + a4.y + a4.z + a4.w + b4.x + b4.y + b4.z + b4.w;
        float ss = a4.x*a4.x + a4.y*a4.y + a4.z*a4.z + a4.w*a4.w
                 + b4.x*b4.x + b4.y*b4.y + b4.z*b4.z + b4.w*b4.w;
        #pragma unroll
        for (int o = 16; o; o >>= 1) {
            s  += __shfl_xor_sync(0xffffffffu, s,  o);
            ss += __shfl_xor_sync(0xffffffffu, ss, o);
        }
        if (grow >= NN) continue;
        float mean = s * (1.f / HH);
        float var  = ss * (1.f / HH) - mean * mean;
        float rstd = rsqrtf(var + 1e-5f);
        float4 g0 = ((const float4*)lng)[lane * 2], g1 = ((const float4*)lng)[lane * 2 + 1];
        float4 c0 = ((const float4*)lnb)[lane * 2], c1 = ((const float4*)lnb)[lane * 2 + 1];
        const float4* hv = (const float4*)(g_jk + (size_t)grow * JKD + (size_t)layer * HH);
        int bidx = __ldg(&batch[grow]);
        const float4* vv = (const float4*)(vn + (size_t)bidx * HH);
        float4 h0 = hv[lane * 2], h1 = hv[lane * 2 + 1];
        float4 w0 = vv[lane * 2], w1 = vv[lane * 2 + 1];
        float4 o0, o1;
        o0.x = fmaxf((a4.x - mean) * rstd * g0.x + c0.x, 0.f) + h0.x + w0.x;
        o0.y = fmaxf((a4.y - mean) * rstd * g0.y + c0.y, 0.f) + h0.y + w0.y;
        o0.z = fmaxf((a4.z - mean) * rstd * g0.z + c0.z, 0.f) + h0.z + w0.z;
        o0.w = fmaxf((a4.w - mean) * rstd * g0.w + c0.w, 0.f) + h0.w + w0.w;
        o1.x = fmaxf((b4.x - mean) * rstd * g1.x + c1.x, 0.f) + h1.x + w1.x;
        o1.y = fmaxf((b4.y - mean) * rstd * g1.y + c1.y, 0.f) + h1.y + w1.y;
        o1.z = fmaxf((b4.z - mean) * rstd * g1.z + c1.z, 0.f) + h1.z + w1.z;
        o1.w = fmaxf((b4.w - mean) * rstd * g1.w + c1.w, 0.f) + h1.w + w1.w;
        float4* jkp = (float4*)(g_jk + (size_t)grow * JKD + (size_t)(layer + 1) * HH);
        jkp[lane * 2]     = o0;
        jkp[lane * 2 + 1] = o1;
    }
}

// ---- head: t = relu(jk @ hw1 + hb1); out = t @ hw2 + hb2 (fused) -----------
__global__ void __launch_bounds__(512, 1)
k_head(const __nv_bfloat16* __restrict__ Bh, const __nv_bfloat16* __restrict__ Bl,
       const float* __restrict__ bias1,
       const float* __restrict__ w2, const float* __restrict__ b2,
       float* __restrict__ out) {
    extern __shared__ __align__(128) char smem[];
    const int tid = threadIdx.x, warp = tid >> 5, lane = tid & 31;
    const int brow = blockIdx.x * 128;
    const int wm = warp & 3, wn = warp >> 2;
    const uint32_t sb = smem_u32(smem);
    const int nch = JKD / 32;   // 48

    const int ar = tid >> 2, aq = tid & 3;
    const float* Ap = g_jk + (size_t)(brow + ar) * JKD + aq * 8;
    const int bplane = tid >> 8, brw = tid & 255;
    const __nv_bfloat16* Bp = (bplane ? Bl : Bh) + (size_t)brw * JKD;

    const uint32_t a_addr = sb + (uint32_t)(wm * 32 + (lane & 15)) * ROWB + (lane >> 4) * 16;
    const int bn = wn * 64 + (lane & 7) + ((lane >> 4) << 3);
    const uint32_t b_addr = sb + 2 * A_SZ + (uint32_t)bn * ROWB + ((lane >> 3) & 1) * 16;

    float acc[2][8][4];
    #pragma unroll
    for (int mi = 0; mi < 2; mi++)
        #pragma unroll
        for (int ni = 0; ni < 8; ni++)
            #pragma unroll
            for (int j = 0; j < 4; j++) acc[mi][ni][j] = 0.f;

    auto ldgA = [&](int c, float f[8]) {
        const float* ap = Ap + c * 32;
        *(float4*)(f)     = *(const float4*)(ap);
        *(float4*)(f + 4) = *(const float4*)(ap + 4);
    };
    auto stsA = [&](int c, const float f[8]) {
        uint32_t hi[4], lo[4];
        #pragma unroll
        for (int q = 0; q < 4; q++) {
            float f0 = f[2*q], f1 = f[2*q+1];
            __nv_bfloat16 h0 = __float2bfloat16(f0), h1 = __float2bfloat16(f1);
            hi[q] = ((uint32_t)__bfloat16_as_ushort(h1) << 16) | __bfloat16_as_ushort(h0);
            lo[q] = pack_bf(f0 - __bfloat162float(h0), f1 - __bfloat162float(h1));
        }
        char* p = smem + (c % 3) * STG + ar * ROWB + aq * 16;
        *(uint4*)(p)        = make_uint4(hi[0], hi[1], hi[2], hi[3]);
        *(uint4*)(p + A_SZ) = make_uint4(lo[0], lo[1], lo[2], lo[3]);
    };
    auto issueB = [&](int c) {
        uint32_t bdst = sb + (c % 3) * STG + 2 * A_SZ + bplane * B_SZ + brw * ROWB;
        const char* bsrc = (const char*)(Bp + c * 32);
        #pragma unroll
        for (int j = 0; j < 4; j++) cpasync16(bdst + j * 16, bsrc + j * 16);
        CP_COMMIT();
    };

    {
        float f0[8], f1[8];
        ldgA(0, f0); issueB(0); stsA(0, f0);
        ldgA(1, f1); issueB(1); stsA(1, f1);
        for (int c = 0; c < nch; c++) {
            if (c + 1 < nch) { CP_WAIT1(); } else { CP_WAIT0(); }
            __syncthreads();
            float fn[8];
            bool pre = (c + 2 < nch);
            if (pre) { ldgA(c + 2, fn); issueB(c + 2); }
            uint32_t so = (c % 3) * STG;
            #pragma unroll
            for (int k16 = 0; k16 < 2; k16++) {
                uint32_t ah[2][4], al[2][4];
                #pragma unroll
                for (int mi = 0; mi < 2; mi++) {
                    uint32_t aa = a_addr + so + mi * 16 * ROWB + k16 * 32;
                    ldmx4(ah[mi], aa);
                    ldmx4(al[mi], aa + A_SZ);
                }
                #pragma unroll
                for (int np = 0; np < 4; np++) {
                    uint32_t ba = b_addr + so + np * 16 * ROWB + k16 * 32;
                    uint32_t bh[4], bl[4];
                    ldmx4(bh, ba);
                    ldmx4(bl, ba + B_SZ);
                    #pragma unroll
                    for (int g = 0; g < 2; g++) {
                        #pragma unroll
                        for (int mi = 0; mi < 2; mi++) {
                            float* cc = acc[mi][np * 2 + g];
                            mma_bf(cc, ah[mi], bh[2*g], bh[2*g+1]);
                            mma_bf(cc, ah[mi], bl[2*g], bl[2*g+1]);
                            mma_bf(cc, al[mi], bh[2*g], bh[2*g+1]);
                        }
                    }
                }
            }
            if (pre) stsA(c + 2, fn);
        }
    }
    __syncthreads();

    // ---- fused head2 --------------------------------------------------------
    float* zs = (float*)smem;
    float* w2s = zs + 128 * ZROW;
    #pragma unroll
    for (int mi = 0; mi < 2; mi++) {
        int rl = wm * 32 + mi * 16 + (lane >> 2);
        #pragma unroll
        for (int ni = 0; ni < 8; ni++) {
            int col = wn * 64 + ni * 8 + (lane & 3) * 2;
            float b0 = __ldg(&bias1[col]), b1v = __ldg(&bias1[col + 1]);
            *(float2*)(zs + (size_t)rl * ZROW + col) =
                make_float2(fmaxf(acc[mi][ni][0] + b0, 0.f), fmaxf(acc[mi][ni][1] + b1v, 0.f));
            *(float2*)(zs + (size_t)(rl + 8) * ZROW + col) =
                make_float2(fmaxf(acc[mi][ni][2] + b0, 0.f), fmaxf(acc[mi][ni][3] + b1v, 0.f));
        }
    }
    for (int i = tid; i < HH * 28; i += 512) w2s[i] = __ldg(&w2[i]);
    __syncthreads();

    #pragma unroll
    for (int rr = 0; rr < 8; rr++) {
        int row = warp * 8 + rr;
        int grow = brow + row;
        if (grow >= NN || lane >= 28) continue;
        const float* zr = zs + (size_t)row * ZROW;
        float a = 0.f;
        #pragma unroll 8
        for (int k = 0; k < HH; k++) a = fmaf(zr[k], w2s[k * 28 + lane], a);
        out[(size_t)grow * 28 + lane] = a + __ldg(&b2[lane]);
    }
}

// ------- virtual node v3: segment-sum aggregation + smem weight tiles -------
#define VG 32
#define VROW 260
#define SMEM_V ((VG * VROW + 64 * HH) * 4)

__global__ void __launch_bounds__(256)
k_vn(const float* __restrict__ w, const float* __restrict__ bias,
     const float* __restrict__ lng, const float* __restrict__ lnb, int layer) {
    extern __shared__ __align__(16) float vsm[];
    float* vnin = vsm;
    float* wt   = vsm + VG * VROW;
    int tid = threadIdx.x;
    int warp = tid >> 5, lane = tid & 31;
    int g0 = blockIdx.x * VG;

    // segment-sum: each warp aggregates 4 graphs from jk slice layer+1
    #pragma unroll
    for (int q = 0; q < 4; q++) {
        int g = warp * 4 + q;
        int gid = g0 + g;
        float4 s0 = f4zero(), s1 = f4zero();
        if (gid < NG) {
            int beg = g_goff[gid], end = g_goff[gid + 1];
            const float* base = g_jk + (size_t)(layer + 1) * HH + lane * 8;
            for (int n = beg; n < end; n++) {
                const float* p = base + (size_t)n * JKD;
                float4 a = *(const float4*)p, b = *(const float4*)(p + 4);
                s0.x += a.x; s0.y += a.y; s0.z += a.z; s0.w += a.w;
                s1.x += b.x; s1.y += b.y; s1.z += b.z; s1.w += b.w;
            }
            const float* vp = g_vn + (size_t)gid * HH + lane * 8;
            float4 v0 = *(const float4*)vp, v1 = *(const float4*)(vp + 4);
            s0.x += v0.x; s0.y += v0.y; s0.z += v0.z; s0.w += v0.w;
            s1.x += v1.x; s1.y += v1.y; s1.z += v1.z; s1.w += v1.w;
        }
        *(float4*)(vnin + g * VROW + lane * 8)     = s0;
        *(float4*)(vnin + g * VROW + lane * 8 + 4) = s1;
    }

    int gl = tid >> 3, sub = tid & 7;
    float acc[32];
    #pragma unroll
    for (int j = 0; j < 32; j++) acc[j] = 0.f;

    for (int kt = 0; kt < 4; kt++) {
        __syncthreads();
        for (int v4 = tid; v4 < 4096; v4 += 256) {
            int k = v4 >> 6, c4 = v4 & 63;
            ((float4*)wt)[k * 64 + c4] = ((const float4*)w)[(size_t)(kt * 64 + k) * 64 + c4];
        }
        __syncthreads();
        for (int k = 0; k < 64; k++) {
            float xv = vnin[gl * VROW + kt * 64 + k];
            const float* wr = wt + k * 256 + sub;
            #pragma unroll
            for (int j = 0; j < 32; j++) acc[j] = fmaf(xv, wr[8 * j], acc[j]);
        }
    }

    float s = 0.f, ss = 0.f;
    float y[32];
    #pragma unroll
    for (int j = 0; j < 32; j++) {
        y[j] = acc[j] + __ldg(&bias[sub + 8 * j]);
        s += y[j]; ss += y[j] * y[j];
    }
    #pragma unroll
    for (int o = 1; o < 8; o <<= 1) {
        s  += __shfl_xor_sync(0xffffffffu, s,  o);
        ss += __shfl_xor_sync(0xffffffffu, ss, o);
    }
    float mean = s * (1.f / HH);
    float var  = ss * (1.f / HH) - mean * mean;
    float rstd = rsqrtf(var + 1e-5f);
    int gid = g0 + gl;
    if (gid < NG) {
        #pragma unroll
        for (int j = 0; j < 32; j++) {
            int col = sub + 8 * j;
            float z = (y[j] - mean) * rstd * __ldg(&lng[col]) + __ldg(&lnb[col]);
            g_vn[(size_t)gid * HH + col] = fmaxf(z, 0.f);
        }
    }
}

// ---------------------------------------------------------------------------
extern "C" void kernel_launch(void* const* d_in, const int* in_sizes, int n_in,
                              void* d_out, int out_size) {
    const int*   x     = (const int*)  d_in[0];
    const int*   ei    = (const int*)  d_in[1];
    const int*   ea    = (const int*)  d_in[2];
    const int*   batch = (const int*)  d_in[3];
    const float* aemb  = (const float*)d_in[4];
    const float* bemb  = (const float*)d_in[5];
    const float* vn0   = (const float*)d_in[6];
    const float* w1    = (const float*)d_in[7];
    const float* b1    = (const float*)d_in[8];
    const float* w2    = (const float*)d_in[9];
    const float* b2    = (const float*)d_in[10];
    const float* eps   = (const float*)d_in[11];
    const float* lng   = (const float*)d_in[12];
    const float* lnb   = (const float*)d_in[13];
    const float* vnw   = (const float*)d_in[14];
    const float* vnb   = (const float*)d_in[15];
    const float* vlg   = (const float*)d_in[16];
    const float* vlb   = (const float*)d_in[17];
    const float* hw1   = (const float*)d_in[18];
    const float* hb1   = (const float*)d_in[19];
    const float* hw2   = (const float*)d_in[20];
    const float* hb2   = (const float*)d_in[21];
    float* out = (float*)d_out;

    float *p_vn;
    cudaGetSymbolAddress((void**)&p_vn, g_vn);
    __nv_bfloat16 *w1h, *w1l, *w2h, *w2l, *hwh, *hwl;
    cudaGetSymbolAddress((void**)&w1h, g_w1t_hi);
    cudaGetSymbolAddress((void**)&w1l, g_w1t_lo);
    cudaGetSymbolAddress((void**)&w2h, g_w2t_hi);
    cudaGetSymbolAddress((void**)&w2l, g_w2t_lo);
    cudaGetSymbolAddress((void**)&hwh, g_hw1t_hi);
    cudaGetSymbolAddress((void**)&hwl, g_hw1t_lo);

    cudaFuncSetAttribute(k_layer, cudaFuncAttributeMaxDynamicSharedMemorySize, SMEM_L);
    cudaFuncSetAttribute(k_head,  cudaFuncAttributeMaxDynamicSharedMemorySize, SMEM_H);
    cudaFuncSetAttribute(k_vn,    cudaFuncAttributeMaxDynamicSharedMemorySize, SMEM_V);

    const int nb_nh = (NN * H4 + 255) / 256;
    const int ggrid = NNP / 128;

    k_prep<<<(NL * HH * HH + 255) / 256, 256>>>(w1, w1h, w1l, HH, HH, NL);
    k_prep<<<(NL * HH * HH + 255) / 256, 256>>>(w2, w2h, w2l, HH, HH, NL);
    k_prep<<<(JKD * HH + 255) / 256, 256>>>(hw1, hwh, hwl, JKD, HH, 1);

    k_embed<<<nb_nh, 256>>>(x, aemb, vn0);
    k_hist<<<(NE + 255) / 256, 256>>>(ei);
    k_scan1<<<NBLK, 256>>>();
    k_scan2<<<1, 256>>>();
    k_scan3<<<NBLK, 256>>>();
    k_fill<<<(NE + 255) / 256, 256>>>(ei, ea, batch);
    k_goff<<<(NN + 255) / 256, 256>>>(batch);

    for (int l = 0; l < NL; l++) {
        k_agg<<<(NN + 7) / 8, 256>>>(bemb, batch, eps, l, x, aemb);
        k_layer<<<ggrid, 512, SMEM_L>>>(
            batch, p_vn, l,
            w1h + (size_t)l * HH * HH, w1l + (size_t)l * HH * HH, b1 + l * HH,
            w2h + (size_t)l * HH * HH, w2l + (size_t)l * HH * HH, b2 + l * HH,
            lng + l * HH, lnb + l * HH);
        if (l < NL - 1)
            k_vn<<<(NG + VG - 1) / VG, 256, SMEM_V>>>(
                vnw + (size_t)l * HH * HH, vnb + l * HH, vlg + l * HH, vlb + l * HH, l);
    }

    k_head<<<ggrid, 512, SMEM_H>>>(hwh, hwl, hb1, hw2, hb2, out);
}